// round 7
// baseline (speedup 1.0000x reference)
#include <cuda_runtime.h>
#include <cuda_bf16.h>
#include <cstdint>

#define NEGV (-1e30f)

// ============================ scratch (device globals) ============================
static __device__ __nv_bfloat16 g_xhi[33554432], g_xlo[33554432];   // x split [16*2048,1024]
static __device__ __nv_bfloat16 g_yhi[33554432], g_ylo[33554432];   // y split
static __device__ __nv_bfloat16 g_wxhi[1048576], g_wxlo[1048576];   // Wx split [1024,1024]
static __device__ __nv_bfloat16 g_wyhi[1048576], g_wylo[1048576];
static __device__ __nv_bfloat16 g_pxhi[33554432], g_pxlo[33554432]; // relu proj splits
static __device__ __nv_bfloat16 g_pyhi[33554432], g_pylo[33554432];
static __device__ float         g_s[67108864];                      // [16,2048,2048] masked scores
static __device__ __nv_bfloat16 g_Phi[67108864], g_Plo[67108864];   // row-softmax probs [i,j]
static __device__ __nv_bfloat16 g_Pchi[67108864], g_Pclo[67108864]; // col-softmax probs transposed [j,i]
static __device__ __nv_bfloat16 g_yThi[33554432], g_yTlo[33554432]; // y^T [d,j]
static __device__ __nv_bfloat16 g_xThi[33554432], g_xTlo[33554432]; // x^T [d,i]
static __device__ float g_cmax[32768], g_cinv[32768];
static __device__ int   g_mask_mode;

// ============================ helpers =============================================
static __device__ __forceinline__ uint32_t smem_u32(const void* p) {
    uint32_t a;
    asm("{ .reg .u64 t; cvta.to.shared.u64 t, %1; cvt.u32.u64 %0, t; }" : "=r"(a) : "l"(p));
    return a;
}

#define LDSM4(R, A)                                                                   \
    asm volatile("ldmatrix.sync.aligned.m8n8.x4.shared.b16 {%0,%1,%2,%3}, [%4];"      \
        : "=r"((R)[0]), "=r"((R)[1]), "=r"((R)[2]), "=r"((R)[3]) : "r"(A))

#define MMA_BF16(C, A, B0, B1)                                                        \
    asm volatile("mma.sync.aligned.m16n8k16.row.col.f32.bf16.bf16.f32 "               \
        "{%0,%1,%2,%3},{%4,%5,%6,%7},{%8,%9},{%0,%1,%2,%3};"                          \
        : "+f"((C)[0]), "+f"((C)[1]), "+f"((C)[2]), "+f"((C)[3])                      \
        : "r"((A)[0]), "r"((A)[1]), "r"((A)[2]), "r"((A)[3]), "r"(B0), "r"(B1))

__global__ void detect_mask_kernel(const unsigned char* __restrict__ xm) {
    if (threadIdx.x == 0 && blockIdx.x == 0) {
        unsigned int c1 = 0, c3 = 0;
        for (int k = 0; k < 4096; k += 4) { c1 |= xm[k + 1]; c3 |= xm[k + 3]; }
        g_mask_mode = c1 ? 0 : (c3 ? 2 : 1);
    }
}
__device__ __forceinline__ bool mask_at(const void* p, int idx, int mode) {
    if (mode == 0) return ((const unsigned char*)p)[idx] != 0;
    if (mode == 1) return ((const int*)p)[idx] != 0;
    return ((const float*)p)[idx] != 0.0f;
}

__device__ __forceinline__ void split2(float v, __nv_bfloat16& h, __nv_bfloat16& l) {
    h = __float2bfloat16(v);
    l = __float2bfloat16(v - __bfloat162float(h));
}

// ============================ weight split kernel =================================
__global__ void split_plain_kernel(const float* __restrict__ src, int which, int n) {
    __nv_bfloat16 *H, *L;
    if (which == 2) { H = g_wxhi; L = g_wxlo; }
    else            { H = g_wyhi; L = g_wylo; }
    int i4 = (blockIdx.x * 256 + threadIdx.x) * 4;
    if (i4 >= n) return;
    float4 v = *reinterpret_cast<const float4*>(src + i4);
    __nv_bfloat16 h0, l0, h1, l1, h2, l2, h3, l3;
    split2(v.x, h0, l0); split2(v.y, h1, l1); split2(v.z, h2, l2); split2(v.w, h3, l3);
    ushort4 Hp = { __bfloat16_as_ushort(h0), __bfloat16_as_ushort(h1),
                   __bfloat16_as_ushort(h2), __bfloat16_as_ushort(h3) };
    ushort4 Lp = { __bfloat16_as_ushort(l0), __bfloat16_as_ushort(l1),
                   __bfloat16_as_ushort(l2), __bfloat16_as_ushort(l3) };
    *reinterpret_cast<ushort4*>(H + i4) = Hp;
    *reinterpret_cast<ushort4*>(L + i4) = Lp;
}

// ============ fused split + transpose: one fp32 read, both layouts out ============
__global__ void split_both_kernel(const float* __restrict__ src, int which) {
    __nv_bfloat16* H  = which ? g_xhi  : g_yhi;
    __nv_bfloat16* L  = which ? g_xlo  : g_ylo;
    __nv_bfloat16* HT = which ? g_xThi : g_yThi;
    __nv_bfloat16* LT = which ? g_xTlo : g_yTlo;
    __shared__ float sm[64][65];
    const int b = blockIdx.z;
    const int r0 = blockIdx.y * 64, c0 = blockIdx.x * 64;
    const int t = threadIdx.x;
    const float* S = src + (size_t)b * 2048 * 1024;
#pragma unroll
    for (int k = 0; k < 16; k++) {
        int idx = k * 256 + t;
        int r = idx >> 6, c = idx & 63;
        sm[r][c] = S[(size_t)(r0 + r) * 1024 + c0 + c];
    }
    __syncthreads();
    __nv_bfloat16* Hb = H + (size_t)b * 2048 * 1024;
    __nv_bfloat16* Lb = L + (size_t)b * 2048 * 1024;
#pragma unroll
    for (int k = 0; k < 4; k++) {
        int idx = k * 1024 + t * 4;
        int r = idx >> 6, c = idx & 63;
        __nv_bfloat16 h[4], l[4];
#pragma unroll
        for (int q = 0; q < 4; q++) split2(sm[r][c + q], h[q], l[q]);
        ushort4 Hp = { __bfloat16_as_ushort(h[0]), __bfloat16_as_ushort(h[1]),
                       __bfloat16_as_ushort(h[2]), __bfloat16_as_ushort(h[3]) };
        ushort4 Lp = { __bfloat16_as_ushort(l[0]), __bfloat16_as_ushort(l[1]),
                       __bfloat16_as_ushort(l[2]), __bfloat16_as_ushort(l[3]) };
        size_t o = (size_t)(r0 + r) * 1024 + c0 + c;
        *reinterpret_cast<ushort4*>(Hb + o) = Hp;
        *reinterpret_cast<ushort4*>(Lb + o) = Lp;
    }
    __nv_bfloat16* HTb = HT + (size_t)b * 1024 * 2048;
    __nv_bfloat16* LTb = LT + (size_t)b * 1024 * 2048;
#pragma unroll
    for (int k = 0; k < 4; k++) {
        int idx = k * 1024 + t * 4;
        int c = idx >> 6, r = idx & 63;
        __nv_bfloat16 h[4], l[4];
#pragma unroll
        for (int q = 0; q < 4; q++) split2(sm[r + q][c], h[q], l[q]);
        ushort4 Hp = { __bfloat16_as_ushort(h[0]), __bfloat16_as_ushort(h[1]),
                       __bfloat16_as_ushort(h[2]), __bfloat16_as_ushort(h[3]) };
        ushort4 Lp = { __bfloat16_as_ushort(l[0]), __bfloat16_as_ushort(l[1]),
                       __bfloat16_as_ushort(l[2]), __bfloat16_as_ushort(l[3]) };
        size_t o = (size_t)(c0 + c) * 2048 + r0 + r;
        *reinterpret_cast<ushort4*>(HTb + o) = Hp;
        *reinterpret_cast<ushort4*>(LTb + o) = Lp;
    }
}

// ============================ fused row softmax (stats + exp + split) =============
__global__ void row_softmax_kernel() {
    const int row = blockIdx.x;
    const float* sp = g_s + (size_t)row * 2048;
    const int t = threadIdx.x;
    float v[8];
    *reinterpret_cast<float4*>(&v[0]) = *reinterpret_cast<const float4*>(sp + t * 8);
    *reinterpret_cast<float4*>(&v[4]) = *reinterpret_cast<const float4*>(sp + t * 8 + 4);
    float m = v[0];
#pragma unroll
    for (int r = 1; r < 8; r++) m = fmaxf(m, v[r]);
    __shared__ float red[256];
    red[t] = m; __syncthreads();
    for (int s = 128; s > 0; s >>= 1) { if (t < s) red[t] = fmaxf(red[t], red[t + s]); __syncthreads(); }
    const float rm = red[0]; __syncthreads();
    float p[8], sum = 0.f;
#pragma unroll
    for (int r = 0; r < 8; r++) { p[r] = __expf(v[r] - rm); sum += p[r]; }
    red[t] = sum; __syncthreads();
    for (int s = 128; s > 0; s >>= 1) { if (t < s) red[t] += red[t + s]; __syncthreads(); }
    const float ri = 1.0f / red[0];
    size_t o = (size_t)row * 2048 + t * 8;
#pragma unroll
    for (int g = 0; g < 2; g++) {
        __nv_bfloat16 h[4], l[4];
#pragma unroll
        for (int q = 0; q < 4; q++) split2(p[g * 4 + q] * ri, h[q], l[q]);
        ushort4 Hp = { __bfloat16_as_ushort(h[0]), __bfloat16_as_ushort(h[1]),
                       __bfloat16_as_ushort(h[2]), __bfloat16_as_ushort(h[3]) };
        ushort4 Lp = { __bfloat16_as_ushort(l[0]), __bfloat16_as_ushort(l[1]),
                       __bfloat16_as_ushort(l[2]), __bfloat16_as_ushort(l[3]) };
        *reinterpret_cast<ushort4*>(g_Phi + o + g * 4) = Hp;
        *reinterpret_cast<ushort4*>(g_Plo + o + g * 4) = Lp;
    }
}

// ============================ col softmax stats ===================================
__global__ void col_stats_kernel() {
    const int b = blockIdx.y;
    const int tx = threadIdx.x, ty = threadIdx.y;
    const int j = blockIdx.x * 32 + tx;
    const float* sp = g_s + (size_t)b * 2048 * 2048 + j;
    float m = -3e38f;
    for (int i = ty; i < 2048; i += 8) m = fmaxf(m, sp[(size_t)i * 2048]);
    __shared__ float red[8][32];
    red[ty][tx] = m; __syncthreads();
    if (ty == 0) {
        float mm = red[0][tx];
#pragma unroll
        for (int r = 1; r < 8; r++) mm = fmaxf(mm, red[r][tx]);
        red[0][tx] = mm;
    }
    __syncthreads();
    const float cm = red[0][tx]; __syncthreads();
    float sum = 0.f;
    for (int i = ty; i < 2048; i += 8) sum += __expf(sp[(size_t)i * 2048] - cm);
    red[ty][tx] = sum; __syncthreads();
    if (ty == 0) {
        float ss = red[0][tx];
#pragma unroll
        for (int r = 1; r < 8; r++) ss += red[r][tx];
        g_cmax[b * 2048 + j] = cm;
        g_cinv[b * 2048 + j] = 1.0f / ss;
    }
}

__global__ void exp_colT_kernel() {
    __shared__ float sm[32][33];
    const int b = blockIdx.z;
    const int i0 = blockIdx.x * 32, j0 = blockIdx.y * 32;
    const int tx = threadIdx.x, ty = threadIdx.y;
    const float* S = g_s + (size_t)b * 2048 * 2048;
    const int j = j0 + tx;
    const float cm = g_cmax[b * 2048 + j], ci = g_cinv[b * 2048 + j];
#pragma unroll
    for (int k = 0; k < 4; k++) {
        int i = ty * 4 + k;
        float v = S[(size_t)(i0 + i) * 2048 + j];
        sm[tx][i] = __expf(v - cm) * ci;
    }
    __syncthreads();
    __nv_bfloat16* Hb = g_Pchi + (size_t)b * 2048 * 2048;
    __nv_bfloat16* Lb = g_Pclo + (size_t)b * 2048 * 2048;
#pragma unroll
    for (int k = 0; k < 4; k++) {
        int jj = ty * 4 + k;
        float v = sm[jj][tx];
        __nv_bfloat16 h, l; split2(v, h, l);
        size_t o = (size_t)(j0 + jj) * 2048 + i0 + tx;
        Hb[o] = h; Lb[o] = l;
    }
}

// ============================ HMMA split GEMM (3-stage pipeline) ==================
// which: 0=proj_x, 1=proj_y, 2=score, 3=attn_row, 4=attn_col
__global__ __launch_bounds__(256, 1)
void gemm_hmma_kernel(int which, float* __restrict__ Cout,
                      const void* __restrict__ XM, const void* __restrict__ YM)
{
    const __nv_bfloat16 *Ah, *Al, *Bh, *Bl;
    size_t sAb = 0, sBb = 0, sCb = 0;
    int lda, ldb, K, ldc, mode;
    float* C = Cout;
    __nv_bfloat16 *Chi = nullptr, *Clo = nullptr;
    if (which == 0) {
        Ah = g_xhi; Al = g_xlo; Bh = g_wxhi; Bl = g_wxlo;
        lda = 1024; ldb = 1024; K = 1024; ldc = 1024; mode = 0;
        Chi = g_pxhi; Clo = g_pxlo;
    } else if (which == 1) {
        Ah = g_yhi; Al = g_ylo; Bh = g_wyhi; Bl = g_wylo;
        lda = 1024; ldb = 1024; K = 1024; ldc = 1024; mode = 0;
        Chi = g_pyhi; Clo = g_pylo;
    } else if (which == 2) {
        Ah = g_pxhi; Al = g_pxlo; Bh = g_pyhi; Bl = g_pylo;
        sAb = (size_t)2048 * 1024; sBb = (size_t)2048 * 1024; sCb = (size_t)2048 * 2048;
        lda = 1024; ldb = 1024; K = 1024; ldc = 2048; mode = 1;
        C = g_s;
    } else if (which == 3) {
        Ah = g_Phi; Al = g_Plo; Bh = g_yThi; Bl = g_yTlo;
        sAb = (size_t)2048 * 2048; sBb = (size_t)1024 * 2048; sCb = (size_t)2048 * 1024;
        lda = 2048; ldb = 2048; K = 2048; ldc = 1024; mode = 2;
    } else {
        Ah = g_Pchi; Al = g_Pclo; Bh = g_xThi; Bl = g_xTlo;
        sAb = (size_t)2048 * 2048; sBb = (size_t)1024 * 2048; sCb = (size_t)2048 * 1024;
        lda = 2048; ldb = 2048; K = 2048; ldc = 1024; mode = 2;
    }

    extern __shared__ __align__(16) char smem_raw[];
    const uint32_t sb = smem_u32(smem_raw);
    const int tid = threadIdx.x, wid = tid >> 5, lane = tid & 31;
    const int warp_m = wid & 3, warp_n = wid >> 2;
    const int b = blockIdx.z;
    const int m0 = blockIdx.y * 128, n0 = blockIdx.x * 128;

    const __nv_bfloat16* tp[4] = {
        Ah + (size_t)b * sAb + (size_t)m0 * lda,
        Al + (size_t)b * sAb + (size_t)m0 * lda,
        Bh + (size_t)b * sBb + (size_t)n0 * ldb,
        Bl + (size_t)b * sBb + (size_t)n0 * ldb
    };

    float acc[2][8][4];
#pragma unroll
    for (int i = 0; i < 2; i++)
#pragma unroll
        for (int j = 0; j < 8; j++)
#pragma unroll
            for (int q = 0; q < 4; q++) acc[i][j][q] = 0.0f;

    const uint32_t aoff = (uint32_t)(warp_m * 32 + (lane & 7) + ((lane >> 3) & 1) * 8) * 80
                        + ((lane >> 4) & 1) * 16;
    const uint32_t boff = (uint32_t)(warp_n * 64 + (lane & 7) + (lane >> 4) * 8) * 80
                        + ((lane >> 3) & 1) * 16;

    const int NC = K >> 5;

    auto load_chunk = [&](int ch, int buf) {
#pragma unroll
        for (int i = 0; i < 8; i++) {
            const int o = i >> 1;
            const int idx = ((i & 1) << 8) + tid;
            const int row = idx >> 2, gr = idx & 3;
            const __nv_bfloat16* src = tp[o] + (size_t)row * (o < 2 ? lda : ldb) + ch * 32 + gr * 8;
            const uint32_t dst = sb + (uint32_t)buf * 40960 + (uint32_t)o * 10240
                               + (uint32_t)row * 80 + gr * 16;
            asm volatile("cp.async.cg.shared.global [%0], [%1], 16;" :: "r"(dst), "l"(src));
        }
        asm volatile("cp.async.commit_group;");
    };

    // prologue: 2 chunks in flight
    load_chunk(0, 0);
    load_chunk(1, 1);
    int cbuf = 0, pbuf = 2;          // compute buffer, prefetch buffer
    for (int ch = 0; ch < NC; ch++) {
        if (ch + 1 < NC) {
            asm volatile("cp.async.wait_group 1;" ::: "memory");   // chunk ch landed
        } else {
            asm volatile("cp.async.wait_group 0;" ::: "memory");
        }
        __syncthreads();                       // all warps done with buf pbuf (chunk ch-1 compute)
        if (ch + 2 < NC) {
            load_chunk(ch + 2, pbuf);
        }
        const uint32_t base = sb + (uint32_t)cbuf * 40960;
        if (++cbuf == 3) cbuf = 0;
        if (++pbuf == 3) pbuf = 0;
#pragma unroll
        for (int s = 0; s < 2; s++) {
            uint32_t a[2][2][4];
#pragma unroll
            for (int mf = 0; mf < 2; mf++) {
                LDSM4(a[mf][0], base + aoff + mf * 1280 + s * 32);
                LDSM4(a[mf][1], base + 10240 + aoff + mf * 1280 + s * 32);
            }
            uint32_t bh[2][4], bl[2][4];
            LDSM4(bh[0], base + 20480 + boff + s * 32);
            LDSM4(bl[0], base + 30720 + boff + s * 32);
#pragma unroll
            for (int np = 0; np < 4; np++) {
                const int cur = np & 1;
                if (np < 3) {
                    LDSM4(bh[cur ^ 1], base + 20480 + boff + (np + 1) * 1280 + s * 32);
                    LDSM4(bl[cur ^ 1], base + 30720 + boff + (np + 1) * 1280 + s * 32);
                }
#pragma unroll
                for (int mf = 0; mf < 2; mf++) {
#pragma unroll
                    for (int h = 0; h < 2; h++) {
                        const int nf = np * 2 + h;
                        MMA_BF16(acc[mf][nf], a[mf][0], bh[cur][2 * h], bh[cur][2 * h + 1]);
                        MMA_BF16(acc[mf][nf], a[mf][0], bl[cur][2 * h], bl[cur][2 * h + 1]);
                        MMA_BF16(acc[mf][nf], a[mf][1], bh[cur][2 * h], bh[cur][2 * h + 1]);
                    }
                }
            }
        }
    }

    // ------------------------------ epilogue ------------------------------
    const int rg = m0 + warp_m * 32 + (lane >> 2);
    const int cg = n0 + warp_n * 64 + (lane & 3) * 2;
    const int mmode = g_mask_mode;

#pragma unroll
    for (int mf = 0; mf < 2; mf++) {
#pragma unroll
        for (int nf = 0; nf < 8; nf++) {
            const int R = rg + mf * 16;
            const int C0 = cg + nf * 8;
            const float v0 = acc[mf][nf][0], v1 = acc[mf][nf][1];
            const float v2 = acc[mf][nf][2], v3 = acc[mf][nf][3];
            if (mode == 0) {
                float r0 = fmaxf(v0, 0.f), r1 = fmaxf(v1, 0.f);
                float r2 = fmaxf(v2, 0.f), r3 = fmaxf(v3, 0.f);
                __nv_bfloat16 h0, l0, h1, l1, h2, l2, h3, l3;
                split2(r0, h0, l0); split2(r1, h1, l1);
                split2(r2, h2, l2); split2(r3, h3, l3);
                uint32_t hp0 = (uint32_t)__bfloat16_as_ushort(h0) | ((uint32_t)__bfloat16_as_ushort(h1) << 16);
                uint32_t lp0 = (uint32_t)__bfloat16_as_ushort(l0) | ((uint32_t)__bfloat16_as_ushort(l1) << 16);
                uint32_t hp1 = (uint32_t)__bfloat16_as_ushort(h2) | ((uint32_t)__bfloat16_as_ushort(h3) << 16);
                uint32_t lp1 = (uint32_t)__bfloat16_as_ushort(l2) | ((uint32_t)__bfloat16_as_ushort(l3) << 16);
                *reinterpret_cast<uint32_t*>(Chi + (size_t)R * ldc + C0) = hp0;
                *reinterpret_cast<uint32_t*>(Clo + (size_t)R * ldc + C0) = lp0;
                *reinterpret_cast<uint32_t*>(Chi + (size_t)(R + 8) * ldc + C0) = hp1;
                *reinterpret_cast<uint32_t*>(Clo + (size_t)(R + 8) * ldc + C0) = lp1;
            } else if (mode == 1) {
                const bool mjA = mask_at(YM, b * 2048 + C0, mmode);
                const bool mjB = mask_at(YM, b * 2048 + C0 + 1, mmode);
                const bool mi0 = mask_at(XM, b * 2048 + R, mmode);
                const bool mi8 = mask_at(XM, b * 2048 + R + 8, mmode);
                float2 w0 = { (mi0 || mjA) ? NEGV : v0, (mi0 || mjB) ? NEGV : v1 };
                float2 w1 = { (mi8 || mjA) ? NEGV : v2, (mi8 || mjB) ? NEGV : v3 };
                *reinterpret_cast<float2*>(C + (size_t)b * sCb + (size_t)R * ldc + C0) = w0;
                *reinterpret_cast<float2*>(C + (size_t)b * sCb + (size_t)(R + 8) * ldc + C0) = w1;
            } else {
                float2 w0 = { v0, v1 };
                float2 w1 = { v2, v3 };
                *reinterpret_cast<float2*>(C + (size_t)b * sCb + (size_t)R * ldc + C0) = w0;
                *reinterpret_cast<float2*>(C + (size_t)b * sCb + (size_t)(R + 8) * ldc + C0) = w1;
            }
        }
    }
}

// =================================================================================
extern "C" void kernel_launch(void* const* d_in, const int* in_sizes, int n_in,
                              void* d_out, int out_size)
{
    (void)in_sizes; (void)n_in; (void)out_size;
    const float* x  = (const float*)d_in[0];
    const float* y  = (const float*)d_in[1];
    const void*  xm = d_in[2];
    const void*  ym = d_in[3];
    const float* Wx = (const float*)d_in[4];
    const float* Wy = (const float*)d_in[5];
    float* out = (float*)d_out;

    static const int SMEM_GEMM = 122880;   // 3 stages x 40960
    cudaFuncSetAttribute(gemm_hmma_kernel, cudaFuncAttributeMaxDynamicSharedMemorySize, SMEM_GEMM);

    // index 0-2
    split_plain_kernel<<<1024, 256>>>(Wx, 2, 1048576);
    split_both_kernel<<<dim3(16, 32, 16), 256>>>(x, 1);
    detect_mask_kernel<<<1, 32>>>((const unsigned char*)xm);
    // index 3: proj_x GEMM — ncu capture target (harness offset 2 + skip 5 => my #3)
    gemm_hmma_kernel<<<dim3(8, 256, 1), 256, SMEM_GEMM>>>(0, nullptr, nullptr, nullptr);
    // remaining prep
    split_plain_kernel<<<1024, 256>>>(Wy, 3, 1048576);
    split_both_kernel<<<dim3(16, 32, 16), 256>>>(y, 0);
    gemm_hmma_kernel<<<dim3(8, 256, 1), 256, SMEM_GEMM>>>(1, nullptr, nullptr, nullptr);
    // scores (masked fp32 epilogue)
    gemm_hmma_kernel<<<dim3(16, 16, 16), 256, SMEM_GEMM>>>(2, nullptr, xm, ym);
    // softmax: fused row pass; col stats + transpose-exp
    row_softmax_kernel<<<32768, 256>>>();
    col_stats_kernel<<<dim3(64, 16), dim3(32, 8)>>>();
    exp_colT_kernel<<<dim3(64, 64, 16), dim3(32, 8)>>>();
    // attention GEMMs
    gemm_hmma_kernel<<<dim3(8, 16, 16), 256, SMEM_GEMM>>>(3, out, nullptr, nullptr);
    gemm_hmma_kernel<<<dim3(8, 16, 16), 256, SMEM_GEMM>>>(4, out + 33554432, nullptr, nullptr);
}

// round 8
// speedup vs baseline: 1.3646x; 1.3646x over previous
#include <cuda_runtime.h>
#include <cuda_bf16.h>
#include <cstdint>

#define NEGV (-1e30f)

// ============================ scratch (device globals) ============================
static __device__ __nv_bfloat16 g_xhi[33554432], g_xlo[33554432];   // x split [16*2048,1024]
static __device__ __nv_bfloat16 g_yhi[33554432], g_ylo[33554432];   // y split
static __device__ __nv_bfloat16 g_wxhi[1048576], g_wxlo[1048576];   // Wx split [1024,1024]
static __device__ __nv_bfloat16 g_wyhi[1048576], g_wylo[1048576];
static __device__ __nv_bfloat16 g_pxhi[33554432], g_pxlo[33554432]; // relu proj splits
static __device__ __nv_bfloat16 g_pyhi[33554432], g_pylo[33554432];
static __device__ float         g_s[67108864];                      // [16,2048,2048] masked scores
static __device__ __nv_bfloat16 g_Phi[67108864], g_Plo[67108864];   // row-softmax probs [i,j]
static __device__ __nv_bfloat16 g_Pchi[67108864], g_Pclo[67108864]; // col-softmax probs transposed [j,i]
static __device__ __nv_bfloat16 g_yThi[33554432], g_yTlo[33554432]; // y^T [d,j]
static __device__ __nv_bfloat16 g_xThi[33554432], g_xTlo[33554432]; // x^T [d,i]
static __device__ float g_cmax[32768], g_cinv[32768];
static __device__ int   g_mask_mode;

// ============================ helpers =============================================
static __device__ __forceinline__ uint32_t smem_u32(const void* p) {
    uint32_t a;
    asm("{ .reg .u64 t; cvta.to.shared.u64 t, %1; cvt.u32.u64 %0, t; }" : "=r"(a) : "l"(p));
    return a;
}

#define LDSM4(R, A)                                                                   \
    asm volatile("ldmatrix.sync.aligned.m8n8.x4.shared.b16 {%0,%1,%2,%3}, [%4];"      \
        : "=r"((R)[0]), "=r"((R)[1]), "=r"((R)[2]), "=r"((R)[3]) : "r"(A))

#define MMA_BF16(C, A, B0, B1)                                                        \
    asm volatile("mma.sync.aligned.m16n8k16.row.col.f32.bf16.bf16.f32 "               \
        "{%0,%1,%2,%3},{%4,%5,%6,%7},{%8,%9},{%0,%1,%2,%3};"                          \
        : "+f"((C)[0]), "+f"((C)[1]), "+f"((C)[2]), "+f"((C)[3])                      \
        : "r"((A)[0]), "r"((A)[1]), "r"((A)[2]), "r"((A)[3]), "r"(B0), "r"(B1))

__global__ void detect_mask_kernel(const unsigned char* __restrict__ xm) {
    if (threadIdx.x == 0 && blockIdx.x == 0) {
        unsigned int c1 = 0, c3 = 0;
        for (int k = 0; k < 4096; k += 4) { c1 |= xm[k + 1]; c3 |= xm[k + 3]; }
        g_mask_mode = c1 ? 0 : (c3 ? 2 : 1);
    }
}
__device__ __forceinline__ bool mask_at(const void* p, int idx, int mode) {
    if (mode == 0) return ((const unsigned char*)p)[idx] != 0;
    if (mode == 1) return ((const int*)p)[idx] != 0;
    return ((const float*)p)[idx] != 0.0f;
}

__device__ __forceinline__ void split2(float v, __nv_bfloat16& h, __nv_bfloat16& l) {
    h = __float2bfloat16(v);
    l = __float2bfloat16(v - __bfloat162float(h));
}

// ============================ weight split kernel =================================
__global__ void split_plain_kernel(const float* __restrict__ src, int which, int n) {
    __nv_bfloat16 *H, *L;
    if (which == 2) { H = g_wxhi; L = g_wxlo; }
    else            { H = g_wyhi; L = g_wylo; }
    int i4 = (blockIdx.x * 256 + threadIdx.x) * 4;
    if (i4 >= n) return;
    float4 v = *reinterpret_cast<const float4*>(src + i4);
    __nv_bfloat16 h0, l0, h1, l1, h2, l2, h3, l3;
    split2(v.x, h0, l0); split2(v.y, h1, l1); split2(v.z, h2, l2); split2(v.w, h3, l3);
    ushort4 Hp = { __bfloat16_as_ushort(h0), __bfloat16_as_ushort(h1),
                   __bfloat16_as_ushort(h2), __bfloat16_as_ushort(h3) };
    ushort4 Lp = { __bfloat16_as_ushort(l0), __bfloat16_as_ushort(l1),
                   __bfloat16_as_ushort(l2), __bfloat16_as_ushort(l3) };
    *reinterpret_cast<ushort4*>(H + i4) = Hp;
    *reinterpret_cast<ushort4*>(L + i4) = Lp;
}

// ============ fused split + transpose: one fp32 read, both layouts out ============
__global__ void split_both_kernel(const float* __restrict__ src, int which) {
    __nv_bfloat16* H  = which ? g_xhi  : g_yhi;
    __nv_bfloat16* L  = which ? g_xlo  : g_ylo;
    __nv_bfloat16* HT = which ? g_xThi : g_yThi;
    __nv_bfloat16* LT = which ? g_xTlo : g_yTlo;
    __shared__ float sm[64][65];
    const int b = blockIdx.z;
    const int r0 = blockIdx.y * 64, c0 = blockIdx.x * 64;
    const int t = threadIdx.x;
    const float* S = src + (size_t)b * 2048 * 1024;
#pragma unroll
    for (int k = 0; k < 16; k++) {
        int idx = k * 256 + t;
        int r = idx >> 6, c = idx & 63;
        sm[r][c] = S[(size_t)(r0 + r) * 1024 + c0 + c];
    }
    __syncthreads();
    __nv_bfloat16* Hb = H + (size_t)b * 2048 * 1024;
    __nv_bfloat16* Lb = L + (size_t)b * 2048 * 1024;
#pragma unroll
    for (int k = 0; k < 4; k++) {
        int idx = k * 1024 + t * 4;
        int r = idx >> 6, c = idx & 63;
        __nv_bfloat16 h[4], l[4];
#pragma unroll
        for (int q = 0; q < 4; q++) split2(sm[r][c + q], h[q], l[q]);
        ushort4 Hp = { __bfloat16_as_ushort(h[0]), __bfloat16_as_ushort(h[1]),
                       __bfloat16_as_ushort(h[2]), __bfloat16_as_ushort(h[3]) };
        ushort4 Lp = { __bfloat16_as_ushort(l[0]), __bfloat16_as_ushort(l[1]),
                       __bfloat16_as_ushort(l[2]), __bfloat16_as_ushort(l[3]) };
        size_t o = (size_t)(r0 + r) * 1024 + c0 + c;
        *reinterpret_cast<ushort4*>(Hb + o) = Hp;
        *reinterpret_cast<ushort4*>(Lb + o) = Lp;
    }
    __nv_bfloat16* HTb = HT + (size_t)b * 1024 * 2048;
    __nv_bfloat16* LTb = LT + (size_t)b * 1024 * 2048;
#pragma unroll
    for (int k = 0; k < 4; k++) {
        int idx = k * 1024 + t * 4;
        int c = idx >> 6, r = idx & 63;
        __nv_bfloat16 h[4], l[4];
#pragma unroll
        for (int q = 0; q < 4; q++) split2(sm[r + q][c], h[q], l[q]);
        ushort4 Hp = { __bfloat16_as_ushort(h[0]), __bfloat16_as_ushort(h[1]),
                       __bfloat16_as_ushort(h[2]), __bfloat16_as_ushort(h[3]) };
        ushort4 Lp = { __bfloat16_as_ushort(l[0]), __bfloat16_as_ushort(l[1]),
                       __bfloat16_as_ushort(l[2]), __bfloat16_as_ushort(l[3]) };
        size_t o = (size_t)(c0 + c) * 2048 + r0 + r;
        *reinterpret_cast<ushort4*>(HTb + o) = Hp;
        *reinterpret_cast<ushort4*>(LTb + o) = Lp;
    }
}

// ============================ fused row softmax (stats + exp + split) =============
__global__ void row_softmax_kernel() {
    const int row = blockIdx.x;
    const float* sp = g_s + (size_t)row * 2048;
    const int t = threadIdx.x;
    float v[8];
    *reinterpret_cast<float4*>(&v[0]) = *reinterpret_cast<const float4*>(sp + t * 8);
    *reinterpret_cast<float4*>(&v[4]) = *reinterpret_cast<const float4*>(sp + t * 8 + 4);
    float m = v[0];
#pragma unroll
    for (int r = 1; r < 8; r++) m = fmaxf(m, v[r]);
    __shared__ float red[256];
    red[t] = m; __syncthreads();
    for (int s = 128; s > 0; s >>= 1) { if (t < s) red[t] = fmaxf(red[t], red[t + s]); __syncthreads(); }
    const float rm = red[0]; __syncthreads();
    float p[8], sum = 0.f;
#pragma unroll
    for (int r = 0; r < 8; r++) { p[r] = __expf(v[r] - rm); sum += p[r]; }
    red[t] = sum; __syncthreads();
    for (int s = 128; s > 0; s >>= 1) { if (t < s) red[t] += red[t + s]; __syncthreads(); }
    const float ri = 1.0f / red[0];
    size_t o = (size_t)row * 2048 + t * 8;
#pragma unroll
    for (int g = 0; g < 2; g++) {
        __nv_bfloat16 h[4], l[4];
#pragma unroll
        for (int q = 0; q < 4; q++) split2(p[g * 4 + q] * ri, h[q], l[q]);
        ushort4 Hp = { __bfloat16_as_ushort(h[0]), __bfloat16_as_ushort(h[1]),
                       __bfloat16_as_ushort(h[2]), __bfloat16_as_ushort(h[3]) };
        ushort4 Lp = { __bfloat16_as_ushort(l[0]), __bfloat16_as_ushort(l[1]),
                       __bfloat16_as_ushort(l[2]), __bfloat16_as_ushort(l[3]) };
        *reinterpret_cast<ushort4*>(g_Phi + o + g * 4) = Hp;
        *reinterpret_cast<ushort4*>(g_Plo + o + g * 4) = Lp;
    }
}

// ============================ col softmax stats ===================================
__global__ void col_stats_kernel() {
    const int b = blockIdx.y;
    const int tx = threadIdx.x, ty = threadIdx.y;
    const int j = blockIdx.x * 32 + tx;
    const float* sp = g_s + (size_t)b * 2048 * 2048 + j;
    float m = -3e38f;
    for (int i = ty; i < 2048; i += 8) m = fmaxf(m, sp[(size_t)i * 2048]);
    __shared__ float red[8][32];
    red[ty][tx] = m; __syncthreads();
    if (ty == 0) {
        float mm = red[0][tx];
#pragma unroll
        for (int r = 1; r < 8; r++) mm = fmaxf(mm, red[r][tx]);
        red[0][tx] = mm;
    }
    __syncthreads();
    const float cm = red[0][tx]; __syncthreads();
    float sum = 0.f;
    for (int i = ty; i < 2048; i += 8) sum += __expf(sp[(size_t)i * 2048] - cm);
    red[ty][tx] = sum; __syncthreads();
    if (ty == 0) {
        float ss = red[0][tx];
#pragma unroll
        for (int r = 1; r < 8; r++) ss += red[r][tx];
        g_cmax[b * 2048 + j] = cm;
        g_cinv[b * 2048 + j] = 1.0f / ss;
    }
}

__global__ void exp_colT_kernel() {
    __shared__ float sm[32][33];
    const int b = blockIdx.z;
    const int i0 = blockIdx.x * 32, j0 = blockIdx.y * 32;
    const int tx = threadIdx.x, ty = threadIdx.y;
    const float* S = g_s + (size_t)b * 2048 * 2048;
    const int j = j0 + tx;
    const float cm = g_cmax[b * 2048 + j], ci = g_cinv[b * 2048 + j];
#pragma unroll
    for (int k = 0; k < 4; k++) {
        int i = ty * 4 + k;
        float v = S[(size_t)(i0 + i) * 2048 + j];
        sm[tx][i] = __expf(v - cm) * ci;
    }
    __syncthreads();
    __nv_bfloat16* Hb = g_Pchi + (size_t)b * 2048 * 2048;
    __nv_bfloat16* Lb = g_Pclo + (size_t)b * 2048 * 2048;
#pragma unroll
    for (int k = 0; k < 4; k++) {
        int jj = ty * 4 + k;
        float v = sm[jj][tx];
        __nv_bfloat16 h, l; split2(v, h, l);
        size_t o = (size_t)(j0 + jj) * 2048 + i0 + tx;
        Hb[o] = h; Lb[o] = l;
    }
}

// ============ HMMA split GEMM: 3-stage pipeline, swizzled smem, occupancy 2 =======
// which: 0=proj_x, 1=proj_y, 2=score, 3=attn_row, 4=attn_col
// Stage = 4 tiles (Ahi,Alo,Bhi,Blo) x 128 rows x 64B, XOR-swizzled: g' = g ^ ((row>>1)&3)
__global__ __launch_bounds__(256, 2)
void gemm_hmma_kernel(int which, float* __restrict__ Cout,
                      const void* __restrict__ XM, const void* __restrict__ YM)
{
    const __nv_bfloat16 *Ah, *Al, *Bh, *Bl;
    size_t sAb = 0, sBb = 0, sCb = 0;
    int lda, ldb, K, ldc, mode;
    float* C = Cout;
    __nv_bfloat16 *Chi = nullptr, *Clo = nullptr;
    if (which == 0) {
        Ah = g_xhi; Al = g_xlo; Bh = g_wxhi; Bl = g_wxlo;
        lda = 1024; ldb = 1024; K = 1024; ldc = 1024; mode = 0;
        Chi = g_pxhi; Clo = g_pxlo;
    } else if (which == 1) {
        Ah = g_yhi; Al = g_ylo; Bh = g_wyhi; Bl = g_wylo;
        lda = 1024; ldb = 1024; K = 1024; ldc = 1024; mode = 0;
        Chi = g_pyhi; Clo = g_pylo;
    } else if (which == 2) {
        Ah = g_pxhi; Al = g_pxlo; Bh = g_pyhi; Bl = g_pylo;
        sAb = (size_t)2048 * 1024; sBb = (size_t)2048 * 1024; sCb = (size_t)2048 * 2048;
        lda = 1024; ldb = 1024; K = 1024; ldc = 2048; mode = 1;
        C = g_s;
    } else if (which == 3) {
        Ah = g_Phi; Al = g_Plo; Bh = g_yThi; Bl = g_yTlo;
        sAb = (size_t)2048 * 2048; sBb = (size_t)1024 * 2048; sCb = (size_t)2048 * 1024;
        lda = 2048; ldb = 2048; K = 2048; ldc = 1024; mode = 2;
    } else {
        Ah = g_Pchi; Al = g_Pclo; Bh = g_xThi; Bl = g_xTlo;
        sAb = (size_t)2048 * 2048; sBb = (size_t)1024 * 2048; sCb = (size_t)2048 * 1024;
        lda = 2048; ldb = 2048; K = 2048; ldc = 1024; mode = 2;
    }

    extern __shared__ __align__(16) char smem_raw[];
    const uint32_t sb = smem_u32(smem_raw);
    const int tid = threadIdx.x, wid = tid >> 5, lane = tid & 31;
    const int warp_m = wid & 3, warp_n = wid >> 2;
    const int b = blockIdx.z;
    const int m0 = blockIdx.y * 128, n0 = blockIdx.x * 128;

    const __nv_bfloat16* tp[4] = {
        Ah + (size_t)b * sAb + (size_t)m0 * lda,
        Al + (size_t)b * sAb + (size_t)m0 * lda,
        Bh + (size_t)b * sBb + (size_t)n0 * ldb,
        Bl + (size_t)b * sBb + (size_t)n0 * ldb
    };

    float acc[2][8][4];
#pragma unroll
    for (int i = 0; i < 2; i++)
#pragma unroll
        for (int j = 0; j < 8; j++)
#pragma unroll
            for (int q = 0; q < 4; q++) acc[i][j][q] = 0.0f;

    // ldmatrix lane offsets with swizzle folded in.
    // A: row = warp_m*32 + (lane&7) + ((lane>>3)&1)*8 (+8/+16 per frag, swizzle-invariant)
    {
    }
    const int rowA = warp_m * 32 + (lane & 7) + ((lane >> 3) & 1) * 8;
    const int cA = (rowA >> 1) & 3;
    const uint32_t aoff = (uint32_t)rowA * 64 + (uint32_t)((((lane >> 4) & 1) ^ (cA & 1)) * 16);
    const uint32_t sxA = (uint32_t)(cA >> 1);
    const int rowB = warp_n * 64 + (lane & 7) + ((lane >> 4) & 1) * 8;
    const int cB = (rowB >> 1) & 3;
    const uint32_t boff = (uint32_t)rowB * 64 + (uint32_t)((((lane >> 3) & 1) ^ (cB & 1)) * 16);
    const uint32_t sxB = (uint32_t)(cB >> 1);

    const int NC = K >> 5;

    auto load_chunk = [&](int ch, int buf) {
#pragma unroll
        for (int i = 0; i < 8; i++) {
            const int o = i >> 1;
            const int idx = ((i & 1) << 8) + tid;
            const int row = idx >> 2, gr = idx & 3;
            const __nv_bfloat16* src = tp[o] + (size_t)row * (o < 2 ? lda : ldb) + ch * 32 + gr * 8;
            const uint32_t dst = sb + (uint32_t)buf * 32768 + (uint32_t)o * 8192
                               + (uint32_t)row * 64 + (uint32_t)((gr ^ ((row >> 1) & 3)) * 16);
            asm volatile("cp.async.cg.shared.global [%0], [%1], 16;" :: "r"(dst), "l"(src));
        }
        asm volatile("cp.async.commit_group;");
    };

    // prologue: 2 chunks in flight
    load_chunk(0, 0);
    if (NC > 1) load_chunk(1, 1);
    int cbuf = 0, pbuf = 2;
    for (int ch = 0; ch < NC; ch++) {
        if (ch + 1 < NC) {
            asm volatile("cp.async.wait_group 1;" ::: "memory");
        } else {
            asm volatile("cp.async.wait_group 0;" ::: "memory");
        }
        __syncthreads();
        if (ch + 2 < NC) load_chunk(ch + 2, pbuf);
        const uint32_t base = sb + (uint32_t)cbuf * 32768;
        if (++cbuf == 3) cbuf = 0;
        if (++pbuf == 3) pbuf = 0;
#pragma unroll
        for (int s = 0; s < 2; s++) {
            const uint32_t sA = ((uint32_t)s ^ sxA) << 5;
            const uint32_t sB = ((uint32_t)s ^ sxB) << 5;
            uint32_t a[2][2][4];
#pragma unroll
            for (int mf = 0; mf < 2; mf++) {
                LDSM4(a[mf][0], base + aoff + mf * 1024 + sA);
                LDSM4(a[mf][1], base + 8192 + aoff + mf * 1024 + sA);
            }
            uint32_t bh[2][4], bl[2][4];
            LDSM4(bh[0], base + 16384 + boff + sB);
            LDSM4(bl[0], base + 24576 + boff + sB);
#pragma unroll
            for (int np = 0; np < 4; np++) {
                const int cur = np & 1;
                if (np < 3) {
                    LDSM4(bh[cur ^ 1], base + 16384 + boff + (np + 1) * 1024 + sB);
                    LDSM4(bl[cur ^ 1], base + 24576 + boff + (np + 1) * 1024 + sB);
                }
#pragma unroll
                for (int mf = 0; mf < 2; mf++) {
#pragma unroll
                    for (int h = 0; h < 2; h++) {
                        const int nf = np * 2 + h;
                        MMA_BF16(acc[mf][nf], a[mf][0], bh[cur][2 * h], bh[cur][2 * h + 1]);
                        MMA_BF16(acc[mf][nf], a[mf][0], bl[cur][2 * h], bl[cur][2 * h + 1]);
                        MMA_BF16(acc[mf][nf], a[mf][1], bh[cur][2 * h], bh[cur][2 * h + 1]);
                    }
                }
            }
        }
    }

    // ------------------------------ epilogue ------------------------------
    const int rg = m0 + warp_m * 32 + (lane >> 2);
    const int cg = n0 + warp_n * 64 + (lane & 3) * 2;
    const int mmode = g_mask_mode;

#pragma unroll
    for (int mf = 0; mf < 2; mf++) {
#pragma unroll
        for (int nf = 0; nf < 8; nf++) {
            const int R = rg + mf * 16;
            const int C0 = cg + nf * 8;
            const float v0 = acc[mf][nf][0], v1 = acc[mf][nf][1];
            const float v2 = acc[mf][nf][2], v3 = acc[mf][nf][3];
            if (mode == 0) {
                float r0 = fmaxf(v0, 0.f), r1 = fmaxf(v1, 0.f);
                float r2 = fmaxf(v2, 0.f), r3 = fmaxf(v3, 0.f);
                __nv_bfloat16 h0, l0, h1, l1, h2, l2, h3, l3;
                split2(r0, h0, l0); split2(r1, h1, l1);
                split2(r2, h2, l2); split2(r3, h3, l3);
                uint32_t hp0 = (uint32_t)__bfloat16_as_ushort(h0) | ((uint32_t)__bfloat16_as_ushort(h1) << 16);
                uint32_t lp0 = (uint32_t)__bfloat16_as_ushort(l0) | ((uint32_t)__bfloat16_as_ushort(l1) << 16);
                uint32_t hp1 = (uint32_t)__bfloat16_as_ushort(h2) | ((uint32_t)__bfloat16_as_ushort(h3) << 16);
                uint32_t lp1 = (uint32_t)__bfloat16_as_ushort(l2) | ((uint32_t)__bfloat16_as_ushort(l3) << 16);
                *reinterpret_cast<uint32_t*>(Chi + (size_t)R * ldc + C0) = hp0;
                *reinterpret_cast<uint32_t*>(Clo + (size_t)R * ldc + C0) = lp0;
                *reinterpret_cast<uint32_t*>(Chi + (size_t)(R + 8) * ldc + C0) = hp1;
                *reinterpret_cast<uint32_t*>(Clo + (size_t)(R + 8) * ldc + C0) = lp1;
            } else if (mode == 1) {
                const bool mjA = mask_at(YM, b * 2048 + C0, mmode);
                const bool mjB = mask_at(YM, b * 2048 + C0 + 1, mmode);
                const bool mi0 = mask_at(XM, b * 2048 + R, mmode);
                const bool mi8 = mask_at(XM, b * 2048 + R + 8, mmode);
                float2 w0 = { (mi0 || mjA) ? NEGV : v0, (mi0 || mjB) ? NEGV : v1 };
                float2 w1 = { (mi8 || mjA) ? NEGV : v2, (mi8 || mjB) ? NEGV : v3 };
                *reinterpret_cast<float2*>(C + (size_t)b * sCb + (size_t)R * ldc + C0) = w0;
                *reinterpret_cast<float2*>(C + (size_t)b * sCb + (size_t)(R + 8) * ldc + C0) = w1;
            } else {
                float2 w0 = { v0, v1 };
                float2 w1 = { v2, v3 };
                *reinterpret_cast<float2*>(C + (size_t)b * sCb + (size_t)R * ldc + C0) = w0;
                *reinterpret_cast<float2*>(C + (size_t)b * sCb + (size_t)(R + 8) * ldc + C0) = w1;
            }
        }
    }
}

// =================================================================================
extern "C" void kernel_launch(void* const* d_in, const int* in_sizes, int n_in,
                              void* d_out, int out_size)
{
    (void)in_sizes; (void)n_in; (void)out_size;
    const float* x  = (const float*)d_in[0];
    const float* y  = (const float*)d_in[1];
    const void*  xm = d_in[2];
    const void*  ym = d_in[3];
    const float* Wx = (const float*)d_in[4];
    const float* Wy = (const float*)d_in[5];
    float* out = (float*)d_out;

    static const int SMEM_GEMM = 98304;   // 3 stages x 32768
    cudaFuncSetAttribute(gemm_hmma_kernel, cudaFuncAttributeMaxDynamicSharedMemorySize, SMEM_GEMM);

    // index 0-2
    split_plain_kernel<<<1024, 256>>>(Wx, 2, 1048576);
    split_both_kernel<<<dim3(16, 32, 16), 256>>>(x, 1);
    detect_mask_kernel<<<1, 32>>>((const unsigned char*)xm);
    // index 3: proj_x GEMM — ncu capture target
    gemm_hmma_kernel<<<dim3(8, 256, 1), 256, SMEM_GEMM>>>(0, nullptr, nullptr, nullptr);
    // remaining prep
    split_plain_kernel<<<1024, 256>>>(Wy, 3, 1048576);
    split_both_kernel<<<dim3(16, 32, 16), 256>>>(y, 0);
    gemm_hmma_kernel<<<dim3(8, 256, 1), 256, SMEM_GEMM>>>(1, nullptr, nullptr, nullptr);
    // scores (masked fp32 epilogue)
    gemm_hmma_kernel<<<dim3(16, 16, 16), 256, SMEM_GEMM>>>(2, nullptr, xm, ym);
    // softmax: fused row pass; col stats + transpose-exp
    row_softmax_kernel<<<32768, 256>>>();
    col_stats_kernel<<<dim3(64, 16), dim3(32, 8)>>>();
    exp_colT_kernel<<<dim3(64, 64, 16), dim3(32, 8)>>>();
    // attention GEMMs
    gemm_hmma_kernel<<<dim3(8, 16, 16), 256, SMEM_GEMM>>>(3, out, nullptr, nullptr);
    gemm_hmma_kernel<<<dim3(8, 16, 16), 256, SMEM_GEMM>>>(4, out + 33554432, nullptr, nullptr);
}

// round 10
// speedup vs baseline: 2.9834x; 2.1863x over previous
#include <cuda_runtime.h>
#include <cuda_bf16.h>
#include <cstdint>

#define NEGV (-1e30f)

// ============================ scratch (device globals) ============================
static __device__ __align__(16) __nv_bfloat16 g_xhi[33554432], g_xlo[33554432];
static __device__ __align__(16) __nv_bfloat16 g_yhi[33554432], g_ylo[33554432];
static __device__ __align__(16) __nv_bfloat16 g_xThi[33554432], g_xTlo[33554432];
static __device__ __align__(16) __nv_bfloat16 g_yThi[33554432], g_yTlo[33554432];
static __device__ __align__(16) __nv_bfloat16 g_wxhi[1048576], g_wxlo[1048576];
static __device__ __align__(16) __nv_bfloat16 g_wyhi[1048576], g_wylo[1048576];
static __device__ __align__(16) __nv_bfloat16 g_pxhi[33554432], g_pxlo[33554432];
static __device__ __align__(16) __nv_bfloat16 g_pyhi[33554432], g_pylo[33554432];
static __device__ __align__(16) float         g_s[67108864];
static __device__ __align__(16) __nv_bfloat16 g_Phi[67108864], g_Plo[67108864];
static __device__ __align__(16) __nv_bfloat16 g_Pchi[67108864], g_Pclo[67108864];
static __device__ __align__(16) float g_cmax[32768], g_cinv[32768];
static __device__ __align__(16) float g_meanX[16384], g_meanY[16384];
static __device__ __align__(16) int   g_idxX[32768], g_idxY[32768];
static __device__ __align__(16) int   g_cntX[16], g_cntXp[16], g_cntY[16], g_cntYp[16];
static __device__ int   g_mask_mode;

// ============================ helpers =============================================
static __device__ __forceinline__ uint32_t smem_u32(const void* p) {
    uint32_t a;
    asm("{ .reg .u64 t; cvta.to.shared.u64 t, %1; cvt.u32.u64 %0, t; }" : "=r"(a) : "l"(p));
    return a;
}
__device__ __forceinline__ int c_cnt(int v)  { return v < 0 ? 0 : (v > 2048 ? 2048 : v); }
__device__ __forceinline__ int c_pad(int v)  {
    v &= ~127;
    return v < 128 ? 128 : (v > 2048 ? 2048 : v);
}
__device__ __forceinline__ int c_idx(int v)  { return v < 0 ? 0 : (v > 2047 ? 2047 : v); }

#define LDSM4(R, A)                                                                   \
    asm volatile("ldmatrix.sync.aligned.m8n8.x4.shared.b16 {%0,%1,%2,%3}, [%4];"      \
        : "=r"((R)[0]), "=r"((R)[1]), "=r"((R)[2]), "=r"((R)[3]) : "r"(A))

#define MMA_BF16(C, A, B0, B1)                                                        \
    asm volatile("mma.sync.aligned.m16n8k16.row.col.f32.bf16.bf16.f32 "               \
        "{%0,%1,%2,%3},{%4,%5,%6,%7},{%8,%9},{%0,%1,%2,%3};"                          \
        : "+f"((C)[0]), "+f"((C)[1]), "+f"((C)[2]), "+f"((C)[3])                      \
        : "r"((A)[0]), "r"((A)[1]), "r"((A)[2]), "r"((A)[3]), "r"(B0), "r"(B1))

__device__ __forceinline__ bool mask_at(const void* p, int idx, int mode) {
    if (mode == 0) return ((const unsigned char*)p)[idx] != 0;
    if (mode == 1) return ((const int*)p)[idx] != 0;
    return ((const float*)p)[idx] != 0.0f;
}

__device__ __forceinline__ void split2(float v, __nv_bfloat16& h, __nv_bfloat16& l) {
    h = __float2bfloat16(v);
    l = __float2bfloat16(v - __bfloat162float(h));
}

// ================= build unmasked index list (+ dtype detection) ==================
__global__ void build_idx_kernel(const void* __restrict__ mask, int whichm) {
    const int b = blockIdx.x;
    const int t = threadIdx.x;                 // 256
    __shared__ int smode;
    __shared__ int scnt[256];
    if (t == 0) {
        const unsigned char* mb = (const unsigned char*)mask;
        unsigned a1 = 0, a3 = 0;
        for (int k = 0; k < 4096; k += 4) { a1 |= mb[k + 1]; a3 |= mb[k + 3]; }
        smode = a1 ? 0 : (a3 ? 2 : 1);
        if (b == 0) g_mask_mode = smode;
    }
    __syncthreads();
    const int mode = smode;
    const int base = b * 2048 + t * 8;
    int fl[8], c = 0;
#pragma unroll
    for (int r = 0; r < 8; r++) { fl[r] = mask_at(mask, base + r, mode) ? 0 : 1; c += fl[r]; }
    scnt[t] = c;
    __syncthreads();
    for (int ofs = 1; ofs < 256; ofs <<= 1) {
        int v = (t >= ofs) ? scnt[t - ofs] : 0;
        __syncthreads();
        scnt[t] += v;
        __syncthreads();
    }
    int pos = scnt[t] - c;
    int* idx = (whichm ? g_idxY : g_idxX) + b * 2048;
#pragma unroll
    for (int r = 0; r < 8; r++) if (fl[r]) idx[pos++] = t * 8 + r;
    __syncthreads();
    const int total = c_cnt(scnt[255]);
    // zero-fill tail so any out-of-contract read yields a safe index
    for (int i = total + t; i < 2048; i += 256) idx[i] = 0;
    if (t == 255) {
        (whichm ? g_cntY : g_cntX)[b] = total;
        (whichm ? g_cntYp : g_cntXp)[b] = c_pad(total + 127);
    }
}

// ============================ weight split kernel =================================
__global__ void split_plain_kernel(const float* __restrict__ src, int which, int n) {
    __nv_bfloat16 *H, *L;
    if (which == 2) { H = g_wxhi; L = g_wxlo; }
    else            { H = g_wyhi; L = g_wylo; }
    int i4 = (blockIdx.x * 256 + threadIdx.x) * 4;
    if (i4 >= n) return;
    float4 v = *reinterpret_cast<const float4*>(src + i4);
    __nv_bfloat16 h0, l0, h1, l1, h2, l2, h3, l3;
    split2(v.x, h0, l0); split2(v.y, h1, l1); split2(v.z, h2, l2); split2(v.w, h3, l3);
    ushort4 Hp = { __bfloat16_as_ushort(h0), __bfloat16_as_ushort(h1),
                   __bfloat16_as_ushort(h2), __bfloat16_as_ushort(h3) };
    ushort4 Lp = { __bfloat16_as_ushort(l0), __bfloat16_as_ushort(l1),
                   __bfloat16_as_ushort(l2), __bfloat16_as_ushort(l3) };
    *reinterpret_cast<ushort4*>(H + i4) = Hp;
    *reinterpret_cast<ushort4*>(L + i4) = Lp;
}

// =========== gather + split + transpose: compact rows, both layouts out ===========
__global__ void gather_split_both_kernel(const float* __restrict__ src, int which) {
    const int b = blockIdx.z;
    const int cnt  = c_cnt((which ? g_cntX  : g_cntY )[b]);
    const int cntp = c_pad((which ? g_cntXp : g_cntYp)[b]);
    const int r0 = blockIdx.y * 64;
    if (r0 >= cntp) return;
    const int c0 = blockIdx.x * 64;
    __nv_bfloat16* H  = which ? g_xhi  : g_yhi;
    __nv_bfloat16* L  = which ? g_xlo  : g_ylo;
    __nv_bfloat16* HT = which ? g_xThi : g_yThi;
    __nv_bfloat16* LT = which ? g_xTlo : g_yTlo;
    const int* ib = (which ? g_idxX : g_idxY) + b * 2048;
    __shared__ float sm[64][65];
    const int t = threadIdx.x;
    const float* S = src + (size_t)b * 2048 * 1024;
#pragma unroll
    for (int k = 0; k < 16; k++) {
        int id = k * 256 + t;
        int r = id >> 6, c = id & 63;
        int gr = r0 + r;
        float v = 0.0f;
        if (gr < cnt) v = S[(size_t)c_idx(ib[gr]) * 1024 + c0 + c];
        sm[r][c] = v;
    }
    __syncthreads();
    __nv_bfloat16* Hb = H + (size_t)b * 2048 * 1024;
    __nv_bfloat16* Lb = L + (size_t)b * 2048 * 1024;
#pragma unroll
    for (int k = 0; k < 4; k++) {
        int id = k * 1024 + t * 4;
        int r = id >> 6, c = id & 63;
        __nv_bfloat16 h[4], l[4];
#pragma unroll
        for (int q = 0; q < 4; q++) split2(sm[r][c + q], h[q], l[q]);
        ushort4 Hp = { __bfloat16_as_ushort(h[0]), __bfloat16_as_ushort(h[1]),
                       __bfloat16_as_ushort(h[2]), __bfloat16_as_ushort(h[3]) };
        ushort4 Lp = { __bfloat16_as_ushort(l[0]), __bfloat16_as_ushort(l[1]),
                       __bfloat16_as_ushort(l[2]), __bfloat16_as_ushort(l[3]) };
        size_t o = (size_t)(r0 + r) * 1024 + c0 + c;
        *reinterpret_cast<ushort4*>(Hb + o) = Hp;
        *reinterpret_cast<ushort4*>(Lb + o) = Lp;
    }
    __nv_bfloat16* HTb = HT + (size_t)b * 1024 * 2048;
    __nv_bfloat16* LTb = LT + (size_t)b * 1024 * 2048;
#pragma unroll
    for (int k = 0; k < 4; k++) {
        int id = k * 1024 + t * 4;
        int c = id >> 6, r = id & 63;
        __nv_bfloat16 h[4], l[4];
#pragma unroll
        for (int q = 0; q < 4; q++) split2(sm[r + q][c], h[q], l[q]);
        ushort4 Hp = { __bfloat16_as_ushort(h[0]), __bfloat16_as_ushort(h[1]),
                       __bfloat16_as_ushort(h[2]), __bfloat16_as_ushort(h[3]) };
        ushort4 Lp = { __bfloat16_as_ushort(l[0]), __bfloat16_as_ushort(l[1]),
                       __bfloat16_as_ushort(l[2]), __bfloat16_as_ushort(l[3]) };
        size_t o = (size_t)(c0 + c) * 2048 + r0 + r;
        *reinterpret_cast<ushort4*>(HTb + o) = Hp;
        *reinterpret_cast<ushort4*>(LTb + o) = Lp;
    }
}

// ============================ fused row softmax (compact) =========================
__global__ void row_softmax_kernel() {
    const int b = blockIdx.y;
    const int row = blockIdx.x;
    if (row >= c_pad(g_cntXp[b])) return;
    const int nYp = c_pad(g_cntYp[b]);
    const float* sp = g_s + (size_t)b * 2048 * 2048 + (size_t)row * 2048;
    const int t = threadIdx.x;
    const bool act = (t * 8) < nYp;
    float v[8];
    if (act) {
        *reinterpret_cast<float4*>(&v[0]) = *reinterpret_cast<const float4*>(sp + t * 8);
        *reinterpret_cast<float4*>(&v[4]) = *reinterpret_cast<const float4*>(sp + t * 8 + 4);
    } else {
#pragma unroll
        for (int r = 0; r < 8; r++) v[r] = NEGV;
    }
    float m = v[0];
#pragma unroll
    for (int r = 1; r < 8; r++) m = fmaxf(m, v[r]);
    __shared__ float red[256];
    red[t] = m; __syncthreads();
    for (int s = 128; s > 0; s >>= 1) { if (t < s) red[t] = fmaxf(red[t], red[t + s]); __syncthreads(); }
    const float rm = red[0]; __syncthreads();
    float p[8], sum = 0.f;
#pragma unroll
    for (int r = 0; r < 8; r++) { p[r] = __expf(v[r] - rm); sum += p[r]; }
    red[t] = sum; __syncthreads();
    for (int s = 128; s > 0; s >>= 1) { if (t < s) red[t] += red[t + s]; __syncthreads(); }
    const float ri = (red[0] > 0.f) ? 1.0f / red[0] : 0.f;
    if (!act) return;
    size_t o = (size_t)b * 2048 * 2048 + (size_t)row * 2048 + t * 8;
#pragma unroll
    for (int g = 0; g < 2; g++) {
        __nv_bfloat16 h[4], l[4];
#pragma unroll
        for (int q = 0; q < 4; q++) split2(p[g * 4 + q] * ri, h[q], l[q]);
        ushort4 Hp = { __bfloat16_as_ushort(h[0]), __bfloat16_as_ushort(h[1]),
                       __bfloat16_as_ushort(h[2]), __bfloat16_as_ushort(h[3]) };
        ushort4 Lp = { __bfloat16_as_ushort(l[0]), __bfloat16_as_ushort(l[1]),
                       __bfloat16_as_ushort(l[2]), __bfloat16_as_ushort(l[3]) };
        *reinterpret_cast<ushort4*>(g_Phi + o + g * 4) = Hp;
        *reinterpret_cast<ushort4*>(g_Plo + o + g * 4) = Lp;
    }
}

// ============================ col softmax stats (compact) =========================
__global__ void col_stats_kernel() {
    const int b = blockIdx.y;
    if (blockIdx.x * 32 >= c_pad(g_cntYp[b])) return;
    const int tx = threadIdx.x, ty = threadIdx.y;
    const int j = blockIdx.x * 32 + tx;
    const int nXp = c_pad(g_cntXp[b]);
    const float* sp = g_s + (size_t)b * 2048 * 2048 + j;
    float m = -3e38f;
    for (int i = ty; i < nXp; i += 8) m = fmaxf(m, sp[(size_t)i * 2048]);
    __shared__ float red[8][32];
    red[ty][tx] = m; __syncthreads();
    if (ty == 0) {
        float mm = red[0][tx];
#pragma unroll
        for (int r = 1; r < 8; r++) mm = fmaxf(mm, red[r][tx]);
        red[0][tx] = mm;
    }
    __syncthreads();
    const float cm = red[0][tx]; __syncthreads();
    float sum = 0.f;
    for (int i = ty; i < nXp; i += 8) sum += __expf(sp[(size_t)i * 2048] - cm);
    red[ty][tx] = sum; __syncthreads();
    if (ty == 0) {
        float ss = red[0][tx];
#pragma unroll
        for (int r = 1; r < 8; r++) ss += red[r][tx];
        g_cmax[b * 2048 + j] = cm;
        g_cinv[b * 2048 + j] = (ss > 0.f) ? 1.0f / ss : 0.f;
    }
}

__global__ void exp_colT_kernel() {
    const int b = blockIdx.z;
    const int i0 = blockIdx.x * 32, j0 = blockIdx.y * 32;
    if (i0 >= c_pad(g_cntXp[b]) || j0 >= c_pad(g_cntYp[b])) return;
    __shared__ float sm[32][33];
    const int tx = threadIdx.x, ty = threadIdx.y;
    const float* S = g_s + (size_t)b * 2048 * 2048;
    const int j = j0 + tx;
    const float cm = g_cmax[b * 2048 + j], ci = g_cinv[b * 2048 + j];
#pragma unroll
    for (int k = 0; k < 4; k++) {
        int i = ty * 4 + k;
        float v = S[(size_t)(i0 + i) * 2048 + j];
        sm[tx][i] = __expf(v - cm) * ci;
    }
    __syncthreads();
    __nv_bfloat16* Hb = g_Pchi;
    __nv_bfloat16* Lb = g_Pclo;
#pragma unroll
    for (int k = 0; k < 4; k++) {
        int jj = ty * 4 + k;
        float v = sm[jj][tx];
        __nv_bfloat16 h, l; split2(v, h, l);
        size_t o = (size_t)b * 2048 * 2048 + (size_t)(j0 + jj) * 2048 + i0 + tx;
        Hb[o] = h; Lb[o] = l;
    }
}

// ============================ mean + fill kernels =================================
__global__ void mean_kernel(const float* __restrict__ src, float* __restrict__ dst) {
    const int b = blockIdx.y;
    const int d = blockIdx.x * 256 + threadIdx.x;
    const float* S = src + (size_t)b * 2048 * 1024 + d;
    float s0 = 0, s1 = 0, s2 = 0, s3 = 0;
    for (int i = 0; i < 2048; i += 4) {
        s0 += S[(size_t)i * 1024];
        s1 += S[(size_t)(i + 1) * 1024];
        s2 += S[(size_t)(i + 2) * 1024];
        s3 += S[(size_t)(i + 3) * 1024];
    }
    dst[b * 1024 + d] = (s0 + s1 + s2 + s3) * (1.0f / 2048.0f);
}

__global__ void mean_fill_kernel(const void* __restrict__ mask,
                                 const float* __restrict__ mean,
                                 float* __restrict__ out) {
    const int b = blockIdx.y;
    const int i = blockIdx.x;
    if (!mask_at(mask, b * 2048 + i, g_mask_mode)) return;
    const int t = threadIdx.x;
    float4 v = *reinterpret_cast<const float4*>(mean + b * 1024 + t * 4);
    *reinterpret_cast<float4*>(out + (size_t)b * 2048 * 1024 + (size_t)i * 1024 + t * 4) = v;
}

// ============ HMMA split GEMM: 3-stage pipeline, swizzled smem, occupancy 2 =======
// which: 0=proj_x, 1=proj_y, 2=score, 3=attn_row, 4=attn_col (all compact)
__global__ __launch_bounds__(256, 2)
void gemm_hmma_kernel(int which, float* __restrict__ Cout)
{
    const int b = blockIdx.z;
    const int m0 = blockIdx.y * 128, n0 = blockIdx.x * 128;

    const __nv_bfloat16 *Ah, *Al, *Bh, *Bl;
    __nv_bfloat16 *Chi = nullptr, *Clo = nullptr;
    float* C = Cout;
    int lda, ldb, K, ldc, mode;
    int Mlim, Nlim = 1 << 30;
    int cRow = 0, cCol = 0;
    const int* scat = nullptr;
    size_t sAb, sBb, cOff;

    if (which <= 1) {
        if (which == 0) { Ah = g_xhi; Al = g_xlo; Bh = g_wxhi; Bl = g_wxlo;
                          Mlim = c_pad(g_cntXp[b]); Chi = g_pxhi; Clo = g_pxlo; }
        else            { Ah = g_yhi; Al = g_ylo; Bh = g_wyhi; Bl = g_wylo;
                          Mlim = c_pad(g_cntYp[b]); Chi = g_pyhi; Clo = g_pylo; }
        lda = 1024; ldb = 1024; K = 1024; ldc = 1024; mode = 0;
        sAb = (size_t)2048 * 1024; sBb = 0; cOff = (size_t)b * 2048 * 1024;
    } else if (which == 2) {
        Ah = g_pxhi; Al = g_pxlo; Bh = g_pyhi; Bl = g_pylo;
        lda = 1024; ldb = 1024; K = 1024; ldc = 2048; mode = 1;
        Mlim = c_pad(g_cntXp[b]); Nlim = c_pad(g_cntYp[b]);
        cRow = c_cnt(g_cntX[b]); cCol = c_cnt(g_cntY[b]);
        C = g_s; sAb = (size_t)2048 * 1024; sBb = (size_t)2048 * 1024;
        cOff = (size_t)b * 2048 * 2048;
    } else if (which == 3) {
        Ah = g_Phi; Al = g_Plo; Bh = g_yThi; Bl = g_yTlo;
        lda = 2048; ldb = 2048; ldc = 1024; mode = 2;
        Mlim = c_pad(g_cntXp[b]); K = c_pad(g_cntYp[b]);
        cRow = c_cnt(g_cntX[b]); scat = g_idxX + b * 2048;
        sAb = (size_t)2048 * 2048; sBb = (size_t)1024 * 2048; cOff = (size_t)b * 2048 * 1024;
    } else {
        Ah = g_Pchi; Al = g_Pclo; Bh = g_xThi; Bl = g_xTlo;
        lda = 2048; ldb = 2048; ldc = 1024; mode = 2;
        Mlim = c_pad(g_cntYp[b]); K = c_pad(g_cntXp[b]);
        cRow = c_cnt(g_cntY[b]); scat = g_idxY + b * 2048;
        sAb = (size_t)2048 * 2048; sBb = (size_t)1024 * 2048; cOff = (size_t)b * 2048 * 1024;
    }
    if (m0 >= Mlim || n0 >= Nlim) return;

    extern __shared__ __align__(16) char smem_raw[];
    const uint32_t sb = smem_u32(smem_raw);
    const int tid = threadIdx.x, wid = tid >> 5, lane = tid & 31;
    const int warp_m = wid & 3, warp_n = wid >> 2;

    const __nv_bfloat16* tp[4] = {
        Ah + (size_t)b * sAb + (size_t)m0 * lda,
        Al + (size_t)b * sAb + (size_t)m0 * lda,
        Bh + (size_t)b * sBb + (size_t)n0 * ldb,
        Bl + (size_t)b * sBb + (size_t)n0 * ldb
    };

    float acc[2][8][4];
#pragma unroll
    for (int i = 0; i < 2; i++)
#pragma unroll
        for (int j = 0; j < 8; j++)
#pragma unroll
            for (int q = 0; q < 4; q++) acc[i][j][q] = 0.0f;

    const int rowA = warp_m * 32 + (lane & 7) + ((lane >> 3) & 1) * 8;
    const int cA = (rowA >> 1) & 3;
    const uint32_t aoff = (uint32_t)rowA * 64 + (uint32_t)((((lane >> 4) & 1) ^ (cA & 1)) * 16);
    const uint32_t sxA = (uint32_t)(cA >> 1);
    const int rowB = warp_n * 64 + (lane & 7) + ((lane >> 4) & 1) * 8;
    const int cB = (rowB >> 1) & 3;
    const uint32_t boff = (uint32_t)rowB * 64 + (uint32_t)((((lane >> 3) & 1) ^ (cB & 1)) * 16);
    const uint32_t sxB = (uint32_t)(cB >> 1);

    const int NC = K >> 5;    // K clamped to [128,2048] multiple of 128 -> NC in [4,64]

    auto load_chunk = [&](int ch, int buf) {
#pragma unroll
        for (int i = 0; i < 8; i++) {
            const int o = i >> 1;
            const int idx = ((i & 1) << 8) + tid;
            const int row = idx >> 2, gr = idx & 3;
            const __nv_bfloat16* src = tp[o] + (size_t)row * (o < 2 ? lda : ldb) + ch * 32 + gr * 8;
            const uint32_t dst = sb + (uint32_t)buf * 32768 + (uint32_t)o * 8192
                               + (uint32_t)row * 64 + (uint32_t)((gr ^ ((row >> 1) & 3)) * 16);
            asm volatile("cp.async.cg.shared.global [%0], [%1], 16;" :: "r"(dst), "l"(src));
        }
        asm volatile("cp.async.commit_group;");
    };

    load_chunk(0, 0);
    load_chunk(1, 1);                       // NC >= 4 guaranteed by clamp
    int cbuf = 0, pbuf = 2;
    for (int ch = 0; ch < NC; ch++) {
        if (ch + 1 < NC) {
            asm volatile("cp.async.wait_group 1;" ::: "memory");
        } else {
            asm volatile("cp.async.wait_group 0;" ::: "memory");
        }
        __syncthreads();
        if (ch + 2 < NC) load_chunk(ch + 2, pbuf);
        const uint32_t base = sb + (uint32_t)cbuf * 32768;
        if (++cbuf == 3) cbuf = 0;
        if (++pbuf == 3) pbuf = 0;
#pragma unroll
        for (int s = 0; s < 2; s++) {
            const uint32_t sA = ((uint32_t)s ^ sxA) << 5;
            const uint32_t sB = ((uint32_t)s ^ sxB) << 5;
            uint32_t a[2][2][4];
#pragma unroll
            for (int mf = 0; mf < 2; mf++) {
                LDSM4(a[mf][0], base + aoff + mf * 1024 + sA);
                LDSM4(a[mf][1], base + 8192 + aoff + mf * 1024 + sA);
            }
            uint32_t bh[2][4], bl[2][4];
            LDSM4(bh[0], base + 16384 + boff + sB);
            LDSM4(bl[0], base + 24576 + boff + sB);
#pragma unroll
            for (int np = 0; np < 4; np++) {
                const int cur = np & 1;
                if (np < 3) {
                    LDSM4(bh[cur ^ 1], base + 16384 + boff + (np + 1) * 1024 + sB);
                    LDSM4(bl[cur ^ 1], base + 24576 + boff + (np + 1) * 1024 + sB);
                }
#pragma unroll
                for (int mf = 0; mf < 2; mf++) {
#pragma unroll
                    for (int h = 0; h < 2; h++) {
                        const int nf = np * 2 + h;
                        MMA_BF16(acc[mf][nf], a[mf][0], bh[cur][2 * h], bh[cur][2 * h + 1]);
                        MMA_BF16(acc[mf][nf], a[mf][0], bl[cur][2 * h], bl[cur][2 * h + 1]);
                        MMA_BF16(acc[mf][nf], a[mf][1], bh[cur][2 * h], bh[cur][2 * h + 1]);
                    }
                }
            }
        }
    }
    asm volatile("cp.async.wait_group 0;" ::: "memory");   // no orphaned async groups

    // ------------------------------ epilogue ------------------------------
    const int rg = m0 + warp_m * 32 + (lane >> 2);
    const int cg = n0 + warp_n * 64 + (lane & 3) * 2;

    if (mode == 0) {
        __nv_bfloat16* CH = Chi + cOff;
        __nv_bfloat16* CL = Clo + cOff;
#pragma unroll
        for (int mf = 0; mf < 2; mf++) {
#pragma unroll
            for (int nf = 0; nf < 8; nf++) {
                const int R = rg + mf * 16;
                const int C0 = cg + nf * 8;
                float r0 = fmaxf(acc[mf][nf][0], 0.f), r1 = fmaxf(acc[mf][nf][1], 0.f);
                float r2 = fmaxf(acc[mf][nf][2], 0.f), r3 = fmaxf(acc[mf][nf][3], 0.f);
                __nv_bfloat16 h0, l0, h1, l1, h2, l2, h3, l3;
                split2(r0, h0, l0); split2(r1, h1, l1);
                split2(r2, h2, l2); split2(r3, h3, l3);
                uint32_t hp0 = (uint32_t)__bfloat16_as_ushort(h0) | ((uint32_t)__bfloat16_as_ushort(h1) << 16);
                uint32_t lp0 = (uint32_t)__bfloat16_as_ushort(l0) | ((uint32_t)__bfloat16_as_ushort(l1) << 16);
                uint32_t hp1 = (uint32_t)__bfloat16_as_ushort(h2) | ((uint32_t)__bfloat16_as_ushort(h3) << 16);
                uint32_t lp1 = (uint32_t)__bfloat16_as_ushort(l2) | ((uint32_t)__bfloat16_as_ushort(l3) << 16);
                *reinterpret_cast<uint32_t*>(CH + (size_t)R * ldc + C0) = hp0;
                *reinterpret_cast<uint32_t*>(CL + (size_t)R * ldc + C0) = lp0;
                *reinterpret_cast<uint32_t*>(CH + (size_t)(R + 8) * ldc + C0) = hp1;
                *reinterpret_cast<uint32_t*>(CL + (size_t)(R + 8) * ldc + C0) = lp1;
            }
        }
    } else if (mode == 1) {
        float* Co = C + cOff;
#pragma unroll
        for (int mf = 0; mf < 2; mf++) {
#pragma unroll
            for (int nf = 0; nf < 8; nf++) {
                const int R0 = rg + mf * 16, R1 = R0 + 8;
                const int C0 = cg + nf * 8;
                const bool c0v = C0 < cCol, c1v = (C0 + 1) < cCol;
                const bool r0v = R0 < cRow, r1v = R1 < cRow;
                float2 w0 = { (r0v && c0v) ? acc[mf][nf][0] : NEGV,
                              (r0v && c1v) ? acc[mf][nf][1] : NEGV };
                float2 w1 = { (r1v && c0v) ? acc[mf][nf][2] : NEGV,
                              (r1v && c1v) ? acc[mf][nf][3] : NEGV };
                *reinterpret_cast<float2*>(Co + (size_t)R0 * ldc + C0) = w0;
                *reinterpret_cast<float2*>(Co + (size_t)R1 * ldc + C0) = w1;
            }
        }
    } else {
        float* Co = Cout + cOff;
        int gr[2][2];
#pragma unroll
        for (int mf = 0; mf < 2; mf++)
#pragma unroll
            for (int h = 0; h < 2; h++) {
                const int R = rg + mf * 16 + h * 8;
                gr[mf][h] = (R < cRow) ? c_idx(scat[R]) : -1;
            }
#pragma unroll
        for (int mf = 0; mf < 2; mf++) {
#pragma unroll
            for (int nf = 0; nf < 8; nf++) {
                const int C0 = cg + nf * 8;
                if (gr[mf][0] >= 0) {
                    float2 w = { acc[mf][nf][0], acc[mf][nf][1] };
                    *reinterpret_cast<float2*>(Co + (size_t)gr[mf][0] * 1024 + C0) = w;
                }
                if (gr[mf][1] >= 0) {
                    float2 w = { acc[mf][nf][2], acc[mf][nf][3] };
                    *reinterpret_cast<float2*>(Co + (size_t)gr[mf][1] * 1024 + C0) = w;
                }
            }
        }
    }
}

// =================================================================================
extern "C" void kernel_launch(void* const* d_in, const int* in_sizes, int n_in,
                              void* d_out, int out_size)
{
    (void)in_sizes; (void)n_in; (void)out_size;
    const float* x  = (const float*)d_in[0];
    const float* y  = (const float*)d_in[1];
    const void*  xm = d_in[2];
    const void*  ym = d_in[3];
    const float* Wx = (const float*)d_in[4];
    const float* Wy = (const float*)d_in[5];
    float* out = (float*)d_out;

    static const int SMEM_GEMM = 98304;   // 3 stages x 32768
    cudaFuncSetAttribute(gemm_hmma_kernel, cudaFuncAttributeMaxDynamicSharedMemorySize, SMEM_GEMM);

    // 0-2: X index build, gather x, Wx split
    build_idx_kernel<<<16, 256>>>(xm, 0);
    gather_split_both_kernel<<<dim3(16, 32, 16), 256>>>(x, 1);
    split_plain_kernel<<<1024, 256>>>(Wx, 2, 1048576);
    // 3: proj_x GEMM — ncu capture target
    gemm_hmma_kernel<<<dim3(8, 16, 16), 256, SMEM_GEMM>>>(0, nullptr);
    // Y side
    build_idx_kernel<<<16, 256>>>(ym, 1);
    gather_split_both_kernel<<<dim3(16, 32, 16), 256>>>(y, 0);
    split_plain_kernel<<<1024, 256>>>(Wy, 3, 1048576);
    gemm_hmma_kernel<<<dim3(8, 16, 16), 256, SMEM_GEMM>>>(1, nullptr);
    // score (compact, NEG-bounded epilogue)
    gemm_hmma_kernel<<<dim3(16, 16, 16), 256, SMEM_GEMM>>>(2, nullptr);
    // softmax passes (compact)
    row_softmax_kernel<<<dim3(2048, 16), 256>>>();
    col_stats_kernel<<<dim3(64, 16), dim3(32, 8)>>>();
    exp_colT_kernel<<<dim3(64, 64, 16), dim3(32, 8)>>>();
    // attention GEMMs (scatter epilogues)
    gemm_hmma_kernel<<<dim3(8, 16, 16), 256, SMEM_GEMM>>>(3, out);
    gemm_hmma_kernel<<<dim3(8, 16, 16), 256, SMEM_GEMM>>>(4, out + 33554432);
    // masked rows: exact means
    mean_kernel<<<dim3(4, 16), 256>>>(y, g_meanY);
    mean_kernel<<<dim3(4, 16), 256>>>(x, g_meanX);
    mean_fill_kernel<<<dim3(2048, 16), 256>>>(xm, g_meanY, out);
    mean_fill_kernel<<<dim3(2048, 16), 256>>>(ym, g_meanX, out + 33554432);
}

// round 11
// speedup vs baseline: 3.3322x; 1.1169x over previous
#include <cuda_runtime.h>
#include <cuda_bf16.h>
#include <cstdint>

#define NEGV (-1e30f)

// ============================ scratch (device globals) ============================
static __device__ __align__(16) __nv_bfloat16 g_xhi[33554432], g_xlo[33554432];
static __device__ __align__(16) __nv_bfloat16 g_yhi[33554432], g_ylo[33554432];
static __device__ __align__(16) __nv_bfloat16 g_xThi[33554432], g_xTlo[33554432];
static __device__ __align__(16) __nv_bfloat16 g_yThi[33554432], g_yTlo[33554432];
static __device__ __align__(16) __nv_bfloat16 g_wxhi[1048576], g_wxlo[1048576];
static __device__ __align__(16) __nv_bfloat16 g_wyhi[1048576], g_wylo[1048576];
static __device__ __align__(16) __nv_bfloat16 g_pxhi[33554432], g_pxlo[33554432];
static __device__ __align__(16) __nv_bfloat16 g_pyhi[33554432], g_pylo[33554432];
static __device__ __align__(16) float         g_s[67108864];
static __device__ __align__(16) __nv_bfloat16 g_Phi[67108864], g_Plo[67108864];
static __device__ __align__(16) __nv_bfloat16 g_Pchi[67108864], g_Pclo[67108864];
static __device__ __align__(16) float g_cmax[32768], g_cinv[32768];
static __device__ __align__(16) float g_meanX[16384], g_meanY[16384];
static __device__ __align__(16) int   g_idxX[32768], g_idxY[32768];
static __device__ __align__(16) int   g_cntX[16], g_cntXp[16], g_cntY[16], g_cntYp[16];
static __device__ int   g_mask_mode;

// ============================ helpers =============================================
static __device__ __forceinline__ uint32_t smem_u32(const void* p) {
    uint32_t a;
    asm("{ .reg .u64 t; cvta.to.shared.u64 t, %1; cvt.u32.u64 %0, t; }" : "=r"(a) : "l"(p));
    return a;
}
__device__ __forceinline__ int c_cnt(int v)  { return v < 0 ? 0 : (v > 2048 ? 2048 : v); }
__device__ __forceinline__ int c_pad(int v)  {
    v &= ~127;
    return v < 128 ? 128 : (v > 2048 ? 2048 : v);
}
__device__ __forceinline__ int c_idx(int v)  { return v < 0 ? 0 : (v > 2047 ? 2047 : v); }

#define LDSM4(R, A)                                                                   \
    asm volatile("ldmatrix.sync.aligned.m8n8.x4.shared.b16 {%0,%1,%2,%3}, [%4];"      \
        : "=r"((R)[0]), "=r"((R)[1]), "=r"((R)[2]), "=r"((R)[3]) : "r"(A))

#define MMA_BF16(C, A, B0, B1)                                                        \
    asm volatile("mma.sync.aligned.m16n8k16.row.col.f32.bf16.bf16.f32 "               \
        "{%0,%1,%2,%3},{%4,%5,%6,%7},{%8,%9},{%0,%1,%2,%3};"                          \
        : "+f"((C)[0]), "+f"((C)[1]), "+f"((C)[2]), "+f"((C)[3])                      \
        : "r"((A)[0]), "r"((A)[1]), "r"((A)[2]), "r"((A)[3]), "r"(B0), "r"(B1))

__device__ __forceinline__ bool mask_at(const void* p, int idx, int mode) {
    if (mode == 0) return ((const unsigned char*)p)[idx] != 0;
    if (mode == 1) return ((const int*)p)[idx] != 0;
    return ((const float*)p)[idx] != 0.0f;
}

__device__ __forceinline__ void split2(float v, __nv_bfloat16& h, __nv_bfloat16& l) {
    h = __float2bfloat16(v);
    l = __float2bfloat16(v - __bfloat162float(h));
}

// ========= build unmasked index lists for BOTH masks (+ dtype detection) ==========
// grid 32: blockIdx.x>>4 = whichm (0=X,1=Y), &15 = batch
__global__ void build_idx_kernel(const void* __restrict__ xm, const void* __restrict__ ym) {
    const int whichm = blockIdx.x >> 4;
    const int b = blockIdx.x & 15;
    const void* mask = whichm ? ym : xm;
    const int t = threadIdx.x;                 // 256
    __shared__ int smode;
    __shared__ int scnt[256];
    if (t == 0) {
        const unsigned char* mb = (const unsigned char*)mask;
        unsigned a1 = 0, a3 = 0;
        for (int k = 0; k < 4096; k += 4) { a1 |= mb[k + 1]; a3 |= mb[k + 3]; }
        smode = a1 ? 0 : (a3 ? 2 : 1);
        if (b == 0 && whichm == 0) g_mask_mode = smode;
    }
    __syncthreads();
    const int mode = smode;
    const int base = b * 2048 + t * 8;
    int fl[8], c = 0;
#pragma unroll
    for (int r = 0; r < 8; r++) { fl[r] = mask_at(mask, base + r, mode) ? 0 : 1; c += fl[r]; }
    scnt[t] = c;
    __syncthreads();
    for (int ofs = 1; ofs < 256; ofs <<= 1) {
        int v = (t >= ofs) ? scnt[t - ofs] : 0;
        __syncthreads();
        scnt[t] += v;
        __syncthreads();
    }
    int pos = scnt[t] - c;
    int* idx = (whichm ? g_idxY : g_idxX) + b * 2048;
#pragma unroll
    for (int r = 0; r < 8; r++) if (fl[r]) idx[pos++] = t * 8 + r;
    __syncthreads();
    const int total = c_cnt(scnt[255]);
    for (int i = total + t; i < 2048; i += 256) idx[i] = 0;
    if (t == 255) {
        (whichm ? g_cntY : g_cntX)[b] = total;
        (whichm ? g_cntYp : g_cntXp)[b] = c_pad(total + 127);
    }
}

// ====================== weight split kernel (both weights) ========================
__global__ void split_plain_kernel(const float* __restrict__ Wx, const float* __restrict__ Wy) {
    const int blk = blockIdx.x;          // 2048: first 1024 Wx, rest Wy
    const int wsel = blk >> 10;
    const float* src = wsel ? Wy : Wx;
    __nv_bfloat16* H = wsel ? g_wyhi : g_wxhi;
    __nv_bfloat16* L = wsel ? g_wylo : g_wxlo;
    int i4 = ((blk & 1023) * 256 + threadIdx.x) * 4;
    float4 v = *reinterpret_cast<const float4*>(src + i4);
    __nv_bfloat16 h0, l0, h1, l1, h2, l2, h3, l3;
    split2(v.x, h0, l0); split2(v.y, h1, l1); split2(v.z, h2, l2); split2(v.w, h3, l3);
    ushort4 Hp = { __bfloat16_as_ushort(h0), __bfloat16_as_ushort(h1),
                   __bfloat16_as_ushort(h2), __bfloat16_as_ushort(h3) };
    ushort4 Lp = { __bfloat16_as_ushort(l0), __bfloat16_as_ushort(l1),
                   __bfloat16_as_ushort(l2), __bfloat16_as_ushort(l3) };
    *reinterpret_cast<ushort4*>(H + i4) = Hp;
    *reinterpret_cast<ushort4*>(L + i4) = Lp;
}

// ====== gather + split + transpose for BOTH tensors (z<16 -> x, z>=16 -> y) =======
__global__ void gather_split_both_kernel(const float* __restrict__ x, const float* __restrict__ y) {
    const int zz = blockIdx.z;
    const int isx = (zz < 16) ? 1 : 0;
    const int b = zz & 15;
    const float* src = isx ? x : y;
    const int cnt  = c_cnt((isx ? g_cntX  : g_cntY )[b]);
    const int cntp = c_pad((isx ? g_cntXp : g_cntYp)[b]);
    const int r0 = blockIdx.y * 64;
    if (r0 >= cntp) return;
    const int c0 = blockIdx.x * 64;
    __nv_bfloat16* H  = isx ? g_xhi  : g_yhi;
    __nv_bfloat16* L  = isx ? g_xlo  : g_ylo;
    __nv_bfloat16* HT = isx ? g_xThi : g_yThi;
    __nv_bfloat16* LT = isx ? g_xTlo : g_yTlo;
    const int* ib = (isx ? g_idxX : g_idxY) + b * 2048;
    __shared__ float sm[64][65];
    const int t = threadIdx.x;
    const float* S = src + (size_t)b * 2048 * 1024;
#pragma unroll
    for (int k = 0; k < 16; k++) {
        int id = k * 256 + t;
        int r = id >> 6, c = id & 63;
        int gr = r0 + r;
        float v = 0.0f;
        if (gr < cnt) v = S[(size_t)c_idx(ib[gr]) * 1024 + c0 + c];
        sm[r][c] = v;
    }
    __syncthreads();
    __nv_bfloat16* Hb = H + (size_t)b * 2048 * 1024;
    __nv_bfloat16* Lb = L + (size_t)b * 2048 * 1024;
#pragma unroll
    for (int k = 0; k < 4; k++) {
        int id = k * 1024 + t * 4;
        int r = id >> 6, c = id & 63;
        __nv_bfloat16 h[4], l[4];
#pragma unroll
        for (int q = 0; q < 4; q++) split2(sm[r][c + q], h[q], l[q]);
        ushort4 Hp = { __bfloat16_as_ushort(h[0]), __bfloat16_as_ushort(h[1]),
                       __bfloat16_as_ushort(h[2]), __bfloat16_as_ushort(h[3]) };
        ushort4 Lp = { __bfloat16_as_ushort(l[0]), __bfloat16_as_ushort(l[1]),
                       __bfloat16_as_ushort(l[2]), __bfloat16_as_ushort(l[3]) };
        size_t o = (size_t)(r0 + r) * 1024 + c0 + c;
        *reinterpret_cast<ushort4*>(Hb + o) = Hp;
        *reinterpret_cast<ushort4*>(Lb + o) = Lp;
    }
    __nv_bfloat16* HTb = HT + (size_t)b * 1024 * 2048;
    __nv_bfloat16* LTb = LT + (size_t)b * 1024 * 2048;
#pragma unroll
    for (int k = 0; k < 4; k++) {
        int id = k * 1024 + t * 4;
        int c = id >> 6, r = id & 63;
        __nv_bfloat16 h[4], l[4];
#pragma unroll
        for (int q = 0; q < 4; q++) split2(sm[r + q][c], h[q], l[q]);
        ushort4 Hp = { __bfloat16_as_ushort(h[0]), __bfloat16_as_ushort(h[1]),
                       __bfloat16_as_ushort(h[2]), __bfloat16_as_ushort(h[3]) };
        ushort4 Lp = { __bfloat16_as_ushort(l[0]), __bfloat16_as_ushort(l[1]),
                       __bfloat16_as_ushort(l[2]), __bfloat16_as_ushort(l[3]) };
        size_t o = (size_t)(c0 + c) * 2048 + r0 + r;
        *reinterpret_cast<ushort4*>(HTb + o) = Hp;
        *reinterpret_cast<ushort4*>(LTb + o) = Lp;
    }
}

// ============================ fused row softmax (compact) =========================
__global__ void row_softmax_kernel() {
    const int b = blockIdx.y;
    const int row = blockIdx.x;
    if (row >= c_pad(g_cntXp[b])) return;
    const int nYp = c_pad(g_cntYp[b]);
    const float* sp = g_s + (size_t)b * 2048 * 2048 + (size_t)row * 2048;
    const int t = threadIdx.x;
    const bool act = (t * 8) < nYp;
    float v[8];
    if (act) {
        *reinterpret_cast<float4*>(&v[0]) = *reinterpret_cast<const float4*>(sp + t * 8);
        *reinterpret_cast<float4*>(&v[4]) = *reinterpret_cast<const float4*>(sp + t * 8 + 4);
    } else {
#pragma unroll
        for (int r = 0; r < 8; r++) v[r] = NEGV;
    }
    float m = v[0];
#pragma unroll
    for (int r = 1; r < 8; r++) m = fmaxf(m, v[r]);
    __shared__ float red[256];
    red[t] = m; __syncthreads();
    for (int s = 128; s > 0; s >>= 1) { if (t < s) red[t] = fmaxf(red[t], red[t + s]); __syncthreads(); }
    const float rm = red[0]; __syncthreads();
    float p[8], sum = 0.f;
#pragma unroll
    for (int r = 0; r < 8; r++) { p[r] = __expf(v[r] - rm); sum += p[r]; }
    red[t] = sum; __syncthreads();
    for (int s = 128; s > 0; s >>= 1) { if (t < s) red[t] += red[t + s]; __syncthreads(); }
    const float ri = (red[0] > 0.f) ? 1.0f / red[0] : 0.f;
    if (!act) return;
    size_t o = (size_t)b * 2048 * 2048 + (size_t)row * 2048 + t * 8;
#pragma unroll
    for (int g = 0; g < 2; g++) {
        __nv_bfloat16 h[4], l[4];
#pragma unroll
        for (int q = 0; q < 4; q++) split2(p[g * 4 + q] * ri, h[q], l[q]);
        ushort4 Hp = { __bfloat16_as_ushort(h[0]), __bfloat16_as_ushort(h[1]),
                       __bfloat16_as_ushort(h[2]), __bfloat16_as_ushort(h[3]) };
        ushort4 Lp = { __bfloat16_as_ushort(l[0]), __bfloat16_as_ushort(l[1]),
                       __bfloat16_as_ushort(l[2]), __bfloat16_as_ushort(l[3]) };
        *reinterpret_cast<ushort4*>(g_Phi + o + g * 4) = Hp;
        *reinterpret_cast<ushort4*>(g_Plo + o + g * 4) = Lp;
    }
}

// ============================ col softmax stats (compact) =========================
__global__ void col_stats_kernel() {
    const int b = blockIdx.y;
    if (blockIdx.x * 32 >= c_pad(g_cntYp[b])) return;
    const int tx = threadIdx.x, ty = threadIdx.y;
    const int j = blockIdx.x * 32 + tx;
    const int nXp = c_pad(g_cntXp[b]);
    const float* sp = g_s + (size_t)b * 2048 * 2048 + j;
    float m = -3e38f;
    for (int i = ty; i < nXp; i += 8) m = fmaxf(m, sp[(size_t)i * 2048]);
    __shared__ float red[8][32];
    red[ty][tx] = m; __syncthreads();
    if (ty == 0) {
        float mm = red[0][tx];
#pragma unroll
        for (int r = 1; r < 8; r++) mm = fmaxf(mm, red[r][tx]);
        red[0][tx] = mm;
    }
    __syncthreads();
    const float cm = red[0][tx]; __syncthreads();
    float sum = 0.f;
    for (int i = ty; i < nXp; i += 8) sum += __expf(sp[(size_t)i * 2048] - cm);
    red[ty][tx] = sum; __syncthreads();
    if (ty == 0) {
        float ss = red[0][tx];
#pragma unroll
        for (int r = 1; r < 8; r++) ss += red[r][tx];
        g_cmax[b * 2048 + j] = cm;
        g_cinv[b * 2048 + j] = (ss > 0.f) ? 1.0f / ss : 0.f;
    }
}

__global__ void exp_colT_kernel() {
    const int b = blockIdx.z;
    const int i0 = blockIdx.x * 32, j0 = blockIdx.y * 32;
    if (i0 >= c_pad(g_cntXp[b]) || j0 >= c_pad(g_cntYp[b])) return;
    __shared__ float sm[32][33];
    const int tx = threadIdx.x, ty = threadIdx.y;
    const float* S = g_s + (size_t)b * 2048 * 2048;
    const int j = j0 + tx;
    const float cm = g_cmax[b * 2048 + j], ci = g_cinv[b * 2048 + j];
#pragma unroll
    for (int k = 0; k < 4; k++) {
        int i = ty * 4 + k;
        float v = S[(size_t)(i0 + i) * 2048 + j];
        sm[tx][i] = __expf(v - cm) * ci;
    }
    __syncthreads();
#pragma unroll
    for (int k = 0; k < 4; k++) {
        int jj = ty * 4 + k;
        float v = sm[jj][tx];
        __nv_bfloat16 h, l; split2(v, h, l);
        size_t o = (size_t)b * 2048 * 2048 + (size_t)(j0 + jj) * 2048 + i0 + tx;
        g_Pchi[o] = h; g_Pclo[o] = l;
    }
}

// ============================ mean + fill kernels (merged) ========================
__global__ void mean_kernel(const float* __restrict__ x, const float* __restrict__ y) {
    const int zz = blockIdx.y;                // 0..31: <16 -> y->meanY, >=16 -> x->meanX
    const int b = zz & 15;
    const float* src = (zz < 16) ? y : x;
    float* dst = (zz < 16) ? g_meanY : g_meanX;
    const int d = blockIdx.x * 256 + threadIdx.x;
    const float* S = src + (size_t)b * 2048 * 1024 + d;
    float s0 = 0, s1 = 0, s2 = 0, s3 = 0;
    for (int i = 0; i < 2048; i += 4) {
        s0 += S[(size_t)i * 1024];
        s1 += S[(size_t)(i + 1) * 1024];
        s2 += S[(size_t)(i + 2) * 1024];
        s3 += S[(size_t)(i + 3) * 1024];
    }
    dst[b * 1024 + d] = (s0 + s1 + s2 + s3) * (1.0f / 2048.0f);
}

__global__ void mean_fill_kernel(const void* __restrict__ xm, const void* __restrict__ ym,
                                 float* __restrict__ out) {
    const int zz = blockIdx.y;                // <16: xm/meanY/out ; >=16: ym/meanX/out+33M
    const int b = zz & 15;
    const void* mask = (zz < 16) ? xm : ym;
    const float* mean = (zz < 16) ? g_meanY : g_meanX;
    float* dst = out + ((zz < 16) ? 0 : 33554432);
    const int i = blockIdx.x;
    if (!mask_at(mask, b * 2048 + i, g_mask_mode)) return;
    const int t = threadIdx.x;
    float4 v = *reinterpret_cast<const float4*>(mean + b * 1024 + t * 4);
    *reinterpret_cast<float4*>(dst + (size_t)b * 2048 * 1024 + (size_t)i * 1024 + t * 4) = v;
}

// ============ HMMA split GEMM: 3-stage pipeline, swizzled smem, occupancy 2 =======
// which: 0 = merged proj (z<16 x-side, z>=16 y-side)
//        2 = score
//        3 = merged attn (z<16 row, z>=16 col)
__global__ __launch_bounds__(256, 2)
void gemm_hmma_kernel(int which, float* __restrict__ Cout)
{
    const int zz = blockIdx.z;
    const int sel = (which == 2) ? 0 : (zz >> 4);
    const int b = (which == 2) ? zz : (zz & 15);
    const int m0 = blockIdx.y * 128, n0 = blockIdx.x * 128;

    const __nv_bfloat16 *Ah, *Al, *Bh, *Bl;
    __nv_bfloat16 *Chi = nullptr, *Clo = nullptr;
    float* C = Cout;
    int lda, ldb, K, ldc, mode;
    int Mlim, Nlim = 1 << 30;
    int cRow = 0, cCol = 0;
    const int* scat = nullptr;
    size_t sAb, sBb, cOff;

    if (which == 0) {
        if (sel == 0) { Ah = g_xhi; Al = g_xlo; Bh = g_wxhi; Bl = g_wxlo;
                        Mlim = c_pad(g_cntXp[b]); Chi = g_pxhi; Clo = g_pxlo; }
        else          { Ah = g_yhi; Al = g_ylo; Bh = g_wyhi; Bl = g_wylo;
                        Mlim = c_pad(g_cntYp[b]); Chi = g_pyhi; Clo = g_pylo; }
        lda = 1024; ldb = 1024; K = 1024; ldc = 1024; mode = 0;
        sAb = (size_t)2048 * 1024; sBb = 0; cOff = (size_t)b * 2048 * 1024;
    } else if (which == 2) {
        Ah = g_pxhi; Al = g_pxlo; Bh = g_pyhi; Bl = g_pylo;
        lda = 1024; ldb = 1024; K = 1024; ldc = 2048; mode = 1;
        Mlim = c_pad(g_cntXp[b]); Nlim = c_pad(g_cntYp[b]);
        cRow = c_cnt(g_cntX[b]); cCol = c_cnt(g_cntY[b]);
        C = g_s; sAb = (size_t)2048 * 1024; sBb = (size_t)2048 * 1024;
        cOff = (size_t)b * 2048 * 2048;
    } else {
        if (sel == 0) {
            Ah = g_Phi; Al = g_Plo; Bh = g_yThi; Bl = g_yTlo;
            Mlim = c_pad(g_cntXp[b]); K = c_pad(g_cntYp[b]);
            cRow = c_cnt(g_cntX[b]); scat = g_idxX + b * 2048;
            cOff = (size_t)b * 2048 * 1024;
        } else {
            Ah = g_Pchi; Al = g_Pclo; Bh = g_xThi; Bl = g_xTlo;
            Mlim = c_pad(g_cntYp[b]); K = c_pad(g_cntXp[b]);
            cRow = c_cnt(g_cntY[b]); scat = g_idxY + b * 2048;
            cOff = (size_t)33554432 + (size_t)b * 2048 * 1024;
        }
        lda = 2048; ldb = 2048; ldc = 1024; mode = 2;
        sAb = (size_t)2048 * 2048; sBb = (size_t)1024 * 2048;
    }
    if (m0 >= Mlim || n0 >= Nlim) return;

    extern __shared__ __align__(16) char smem_raw[];
    const uint32_t sb = smem_u32(smem_raw);
    const int tid = threadIdx.x, wid = tid >> 5, lane = tid & 31;
    const int warp_m = wid & 3, warp_n = wid >> 2;

    const __nv_bfloat16* tp[4] = {
        Ah + (size_t)b * sAb + (size_t)m0 * lda,
        Al + (size_t)b * sAb + (size_t)m0 * lda,
        Bh + (size_t)b * sBb + (size_t)n0 * ldb,
        Bl + (size_t)b * sBb + (size_t)n0 * ldb
    };

    float acc[2][8][4];
#pragma unroll
    for (int i = 0; i < 2; i++)
#pragma unroll
        for (int j = 0; j < 8; j++)
#pragma unroll
            for (int q = 0; q < 4; q++) acc[i][j][q] = 0.0f;

    const int rowA = warp_m * 32 + (lane & 7) + ((lane >> 3) & 1) * 8;
    const int cA = (rowA >> 1) & 3;
    const uint32_t aoff = (uint32_t)rowA * 64 + (uint32_t)((((lane >> 4) & 1) ^ (cA & 1)) * 16);
    const uint32_t sxA = (uint32_t)(cA >> 1);
    const int rowB = warp_n * 64 + (lane & 7) + ((lane >> 4) & 1) * 8;
    const int cB = (rowB >> 1) & 3;
    const uint32_t boff = (uint32_t)rowB * 64 + (uint32_t)((((lane >> 3) & 1) ^ (cB & 1)) * 16);
    const uint32_t sxB = (uint32_t)(cB >> 1);

    const int NC = K >> 5;    // clamped K -> NC in [4,64]

    auto load_chunk = [&](int ch, int buf) {
#pragma unroll
        for (int i = 0; i < 8; i++) {
            const int o = i >> 1;
            const int idx = ((i & 1) << 8) + tid;
            const int row = idx >> 2, gr = idx & 3;
            const __nv_bfloat16* src = tp[o] + (size_t)row * (o < 2 ? lda : ldb) + ch * 32 + gr * 8;
            const uint32_t dst = sb + (uint32_t)buf * 32768 + (uint32_t)o * 8192
                               + (uint32_t)row * 64 + (uint32_t)((gr ^ ((row >> 1) & 3)) * 16);
            asm volatile("cp.async.cg.shared.global [%0], [%1], 16;" :: "r"(dst), "l"(src));
        }
        asm volatile("cp.async.commit_group;");
    };

    load_chunk(0, 0);
    load_chunk(1, 1);
    int cbuf = 0, pbuf = 2;
    for (int ch = 0; ch < NC; ch++) {
        if (ch + 1 < NC) {
            asm volatile("cp.async.wait_group 1;" ::: "memory");
        } else {
            asm volatile("cp.async.wait_group 0;" ::: "memory");
        }
        __syncthreads();
        if (ch + 2 < NC) load_chunk(ch + 2, pbuf);
        const uint32_t base = sb + (uint32_t)cbuf * 32768;
        if (++cbuf == 3) cbuf = 0;
        if (++pbuf == 3) pbuf = 0;
#pragma unroll
        for (int s = 0; s < 2; s++) {
            const uint32_t sA = ((uint32_t)s ^ sxA) << 5;
            const uint32_t sB = ((uint32_t)s ^ sxB) << 5;
            uint32_t a[2][2][4];
#pragma unroll
            for (int mf = 0; mf < 2; mf++) {
                LDSM4(a[mf][0], base + aoff + mf * 1024 + sA);
                LDSM4(a[mf][1], base + 8192 + aoff + mf * 1024 + sA);
            }
            uint32_t bh[2][4], bl[2][4];
            LDSM4(bh[0], base + 16384 + boff + sB);
            LDSM4(bl[0], base + 24576 + boff + sB);
#pragma unroll
            for (int np = 0; np < 4; np++) {
                const int cur = np & 1;
                if (np < 3) {
                    LDSM4(bh[cur ^ 1], base + 16384 + boff + (np + 1) * 1024 + sB);
                    LDSM4(bl[cur ^ 1], base + 24576 + boff + (np + 1) * 1024 + sB);
                }
#pragma unroll
                for (int mf = 0; mf < 2; mf++) {
#pragma unroll
                    for (int h = 0; h < 2; h++) {
                        const int nf = np * 2 + h;
                        MMA_BF16(acc[mf][nf], a[mf][0], bh[cur][2 * h], bh[cur][2 * h + 1]);
                        MMA_BF16(acc[mf][nf], a[mf][0], bl[cur][2 * h], bl[cur][2 * h + 1]);
                        MMA_BF16(acc[mf][nf], a[mf][1], bh[cur][2 * h], bh[cur][2 * h + 1]);
                    }
                }
            }
        }
    }
    asm volatile("cp.async.wait_group 0;" ::: "memory");

    // ------------------------------ epilogue ------------------------------
    const int rg = m0 + warp_m * 32 + (lane >> 2);
    const int cg = n0 + warp_n * 64 + (lane & 3) * 2;

    if (mode == 0) {
        __nv_bfloat16* CH = Chi + cOff;
        __nv_bfloat16* CL = Clo + cOff;
#pragma unroll
        for (int mf = 0; mf < 2; mf++) {
#pragma unroll
            for (int nf = 0; nf < 8; nf++) {
                const int R = rg + mf * 16;
                const int C0 = cg + nf * 8;
                float r0 = fmaxf(acc[mf][nf][0], 0.f), r1 = fmaxf(acc[mf][nf][1], 0.f);
                float r2 = fmaxf(acc[mf][nf][2], 0.f), r3 = fmaxf(acc[mf][nf][3], 0.f);
                __nv_bfloat16 h0, l0, h1, l1, h2, l2, h3, l3;
                split2(r0, h0, l0); split2(r1, h1, l1);
                split2(r2, h2, l2); split2(r3, h3, l3);
                uint32_t hp0 = (uint32_t)__bfloat16_as_ushort(h0) | ((uint32_t)__bfloat16_as_ushort(h1) << 16);
                uint32_t lp0 = (uint32_t)__bfloat16_as_ushort(l0) | ((uint32_t)__bfloat16_as_ushort(l1) << 16);
                uint32_t hp1 = (uint32_t)__bfloat16_as_ushort(h2) | ((uint32_t)__bfloat16_as_ushort(h3) << 16);
                uint32_t lp1 = (uint32_t)__bfloat16_as_ushort(l2) | ((uint32_t)__bfloat16_as_ushort(l3) << 16);
                *reinterpret_cast<uint32_t*>(CH + (size_t)R * ldc + C0) = hp0;
                *reinterpret_cast<uint32_t*>(CL + (size_t)R * ldc + C0) = lp0;
                *reinterpret_cast<uint32_t*>(CH + (size_t)(R + 8) * ldc + C0) = hp1;
                *reinterpret_cast<uint32_t*>(CL + (size_t)(R + 8) * ldc + C0) = lp1;
            }
        }
    } else if (mode == 1) {
        float* Co = C + cOff;
#pragma unroll
        for (int mf = 0; mf < 2; mf++) {
#pragma unroll
            for (int nf = 0; nf < 8; nf++) {
                const int R0 = rg + mf * 16, R1 = R0 + 8;
                const int C0 = cg + nf * 8;
                const bool c0v = C0 < cCol, c1v = (C0 + 1) < cCol;
                const bool r0v = R0 < cRow, r1v = R1 < cRow;
                float2 w0 = { (r0v && c0v) ? acc[mf][nf][0] : NEGV,
                              (r0v && c1v) ? acc[mf][nf][1] : NEGV };
                float2 w1 = { (r1v && c0v) ? acc[mf][nf][2] : NEGV,
                              (r1v && c1v) ? acc[mf][nf][3] : NEGV };
                *reinterpret_cast<float2*>(Co + (size_t)R0 * ldc + C0) = w0;
                *reinterpret_cast<float2*>(Co + (size_t)R1 * ldc + C0) = w1;
            }
        }
    } else {
        float* Co = Cout + cOff;
        int gr[2][2];
#pragma unroll
        for (int mf = 0; mf < 2; mf++)
#pragma unroll
            for (int h = 0; h < 2; h++) {
                const int R = rg + mf * 16 + h * 8;
                gr[mf][h] = (R < cRow) ? c_idx(scat[R]) : -1;
            }
#pragma unroll
        for (int mf = 0; mf < 2; mf++) {
#pragma unroll
            for (int nf = 0; nf < 8; nf++) {
                const int C0 = cg + nf * 8;
                if (gr[mf][0] >= 0) {
                    float2 w = { acc[mf][nf][0], acc[mf][nf][1] };
                    *reinterpret_cast<float2*>(Co + (size_t)gr[mf][0] * 1024 + C0) = w;
                }
                if (gr[mf][1] >= 0) {
                    float2 w = { acc[mf][nf][2], acc[mf][nf][3] };
                    *reinterpret_cast<float2*>(Co + (size_t)gr[mf][1] * 1024 + C0) = w;
                }
            }
        }
    }
}

// =================================================================================
extern "C" void kernel_launch(void* const* d_in, const int* in_sizes, int n_in,
                              void* d_out, int out_size)
{
    (void)in_sizes; (void)n_in; (void)out_size;
    const float* x  = (const float*)d_in[0];
    const float* y  = (const float*)d_in[1];
    const void*  xm = d_in[2];
    const void*  ym = d_in[3];
    const float* Wx = (const float*)d_in[4];
    const float* Wy = (const float*)d_in[5];
    float* out = (float*)d_out;

    static const int SMEM_GEMM = 98304;   // 3 stages x 32768
    cudaFuncSetAttribute(gemm_hmma_kernel, cudaFuncAttributeMaxDynamicSharedMemorySize, SMEM_GEMM);

    // 0-2
    build_idx_kernel<<<32, 256>>>(xm, ym);
    gather_split_both_kernel<<<dim3(16, 32, 32), 256>>>(x, y);
    split_plain_kernel<<<2048, 256>>>(Wx, Wy);
    // 3: merged projection GEMM — ncu capture target
    gemm_hmma_kernel<<<dim3(8, 16, 32), 256, SMEM_GEMM>>>(0, nullptr);
    // score
    gemm_hmma_kernel<<<dim3(16, 16, 16), 256, SMEM_GEMM>>>(2, nullptr);
    // softmax passes
    row_softmax_kernel<<<dim3(2048, 16), 256>>>();
    col_stats_kernel<<<dim3(64, 16), dim3(32, 8)>>>();
    exp_colT_kernel<<<dim3(64, 64, 16), dim3(32, 8)>>>();
    // merged attention GEMMs (scatter epilogues)
    gemm_hmma_kernel<<<dim3(8, 16, 32), 256, SMEM_GEMM>>>(3, out);
    // masked rows: exact means
    mean_kernel<<<dim3(4, 32), 256>>>(x, y);
    mean_fill_kernel<<<dim3(2048, 32), 256>>>(xm, ym, out);
}

// round 12
// speedup vs baseline: 3.3948x; 1.0188x over previous
#include <cuda_runtime.h>
#include <cuda_fp16.h>
#include <cstdint>

#define NEGV (-1e30f)

// ============================ scratch (device globals) ============================
static __device__ __align__(16) __half g_xhi[33554432], g_xlo[33554432];
static __device__ __align__(16) __half g_yhi[33554432], g_ylo[33554432];
static __device__ __align__(16) __half g_xThi[33554432], g_yThi[33554432];  // hi-only transposed
static __device__ __align__(16) __half g_wxhi[1048576], g_wxlo[1048576];
static __device__ __align__(16) __half g_wyhi[1048576], g_wylo[1048576];
static __device__ __align__(16) __half g_pxhi[33554432], g_pxlo[33554432];
static __device__ __align__(16) __half g_pyhi[33554432], g_pylo[33554432];
static __device__ __align__(16) float  g_s[67108864];
static __device__ __align__(16) __half g_Phi[67108864], g_Plo[67108864];
static __device__ __align__(16) __half g_Pchi[67108864], g_Pclo[67108864];
static __device__ __align__(16) float g_cmax[32768], g_cinv[32768];
static __device__ __align__(16) float g_meanX[16384], g_meanY[16384];
static __device__ __align__(16) int   g_idxX[32768], g_idxY[32768];
static __device__ __align__(16) int   g_cntX[16], g_cntXp[16], g_cntY[16], g_cntYp[16];
static __device__ int   g_mask_mode;

// ============================ helpers =============================================
static __device__ __forceinline__ uint32_t smem_u32(const void* p) {
    uint32_t a;
    asm("{ .reg .u64 t; cvta.to.shared.u64 t, %1; cvt.u32.u64 %0, t; }" : "=r"(a) : "l"(p));
    return a;
}
__device__ __forceinline__ int c_cnt(int v)  { return v < 0 ? 0 : (v > 2048 ? 2048 : v); }
__device__ __forceinline__ int c_pad(int v)  {
    v &= ~127;
    return v < 128 ? 128 : (v > 2048 ? 2048 : v);
}
__device__ __forceinline__ int c_idx(int v)  { return v < 0 ? 0 : (v > 2047 ? 2047 : v); }

#define LDSM4(R, A)                                                                   \
    asm volatile("ldmatrix.sync.aligned.m8n8.x4.shared.b16 {%0,%1,%2,%3}, [%4];"      \
        : "=r"((R)[0]), "=r"((R)[1]), "=r"((R)[2]), "=r"((R)[3]) : "r"(A))

#define MMA_F16(C, A, B0, B1)                                                         \
    asm volatile("mma.sync.aligned.m16n8k16.row.col.f32.f16.f16.f32 "                 \
        "{%0,%1,%2,%3},{%4,%5,%6,%7},{%8,%9},{%0,%1,%2,%3};"                          \
        : "+f"((C)[0]), "+f"((C)[1]), "+f"((C)[2]), "+f"((C)[3])                      \
        : "r"((A)[0]), "r"((A)[1]), "r"((A)[2]), "r"((A)[3]), "r"(B0), "r"(B1))

__device__ __forceinline__ bool mask_at(const void* p, int idx, int mode) {
    if (mode == 0) return ((const unsigned char*)p)[idx] != 0;
    if (mode == 1) return ((const int*)p)[idx] != 0;
    return ((const float*)p)[idx] != 0.0f;
}

__device__ __forceinline__ void split2h(float v, __half& h, __half& l) {
    h = __float2half_rn(v);
    l = __float2half_rn(v - __half2float(h));
}

// ========= build unmasked index lists for BOTH masks (+ dtype detection) ==========
__global__ void build_idx_kernel(const void* __restrict__ xm, const void* __restrict__ ym) {
    const int whichm = blockIdx.x >> 4;
    const int b = blockIdx.x & 15;
    const void* mask = whichm ? ym : xm;
    const int t = threadIdx.x;                 // 256
    __shared__ int smode;
    __shared__ int scnt[256];
    if (t == 0) {
        const unsigned char* mb = (const unsigned char*)mask;
        unsigned a1 = 0, a3 = 0;
        for (int k = 0; k < 4096; k += 4) { a1 |= mb[k + 1]; a3 |= mb[k + 3]; }
        smode = a1 ? 0 : (a3 ? 2 : 1);
        if (b == 0 && whichm == 0) g_mask_mode = smode;
    }
    __syncthreads();
    const int mode = smode;
    const int base = b * 2048 + t * 8;
    int fl[8], c = 0;
#pragma unroll
    for (int r = 0; r < 8; r++) { fl[r] = mask_at(mask, base + r, mode) ? 0 : 1; c += fl[r]; }
    scnt[t] = c;
    __syncthreads();
    for (int ofs = 1; ofs < 256; ofs <<= 1) {
        int v = (t >= ofs) ? scnt[t - ofs] : 0;
        __syncthreads();
        scnt[t] += v;
        __syncthreads();
    }
    int pos = scnt[t] - c;
    int* idx = (whichm ? g_idxY : g_idxX) + b * 2048;
#pragma unroll
    for (int r = 0; r < 8; r++) if (fl[r]) idx[pos++] = t * 8 + r;
    __syncthreads();
    const int total = c_cnt(scnt[255]);
    for (int i = total + t; i < 2048; i += 256) idx[i] = 0;
    if (t == 255) {
        (whichm ? g_cntY : g_cntX)[b] = total;
        (whichm ? g_cntYp : g_cntXp)[b] = c_pad(total + 127);
    }
}

// ====================== weight split kernel (both weights) ========================
__global__ void split_plain_kernel(const float* __restrict__ Wx, const float* __restrict__ Wy) {
    const int blk = blockIdx.x;          // 2048: first 1024 Wx, rest Wy
    const int wsel = blk >> 10;
    const float* src = wsel ? Wy : Wx;
    __half* H = wsel ? g_wyhi : g_wxhi;
    __half* L = wsel ? g_wylo : g_wxlo;
    int i4 = ((blk & 1023) * 256 + threadIdx.x) * 4;
    float4 v = *reinterpret_cast<const float4*>(src + i4);
    __half h0, l0, h1, l1, h2, l2, h3, l3;
    split2h(v.x, h0, l0); split2h(v.y, h1, l1); split2h(v.z, h2, l2); split2h(v.w, h3, l3);
    ushort4 Hp = { __half_as_ushort(h0), __half_as_ushort(h1),
                   __half_as_ushort(h2), __half_as_ushort(h3) };
    ushort4 Lp = { __half_as_ushort(l0), __half_as_ushort(l1),
                   __half_as_ushort(l2), __half_as_ushort(l3) };
    *reinterpret_cast<ushort4*>(H + i4) = Hp;
    *reinterpret_cast<ushort4*>(L + i4) = Lp;
}

// ====== gather + split + transpose for BOTH tensors (z<16 -> x, z>=16 -> y) =======
// row-major: fp16 hi/lo; transposed: fp16 hi only
__global__ void gather_split_both_kernel(const float* __restrict__ x, const float* __restrict__ y) {
    const int zz = blockIdx.z;
    const int isx = (zz < 16) ? 1 : 0;
    const int b = zz & 15;
    const float* src = isx ? x : y;
    const int cnt  = c_cnt((isx ? g_cntX  : g_cntY )[b]);
    const int cntp = c_pad((isx ? g_cntXp : g_cntYp)[b]);
    const int r0 = blockIdx.y * 64;
    if (r0 >= cntp) return;
    const int c0 = blockIdx.x * 64;
    __half* H  = isx ? g_xhi  : g_yhi;
    __half* L  = isx ? g_xlo  : g_ylo;
    __half* HT = isx ? g_xThi : g_yThi;
    const int* ib = (isx ? g_idxX : g_idxY) + b * 2048;
    __shared__ float sm[64][65];
    const int t = threadIdx.x;
    const float* S = src + (size_t)b * 2048 * 1024;
#pragma unroll
    for (int k = 0; k < 16; k++) {
        int id = k * 256 + t;
        int r = id >> 6, c = id & 63;
        int gr = r0 + r;
        float v = 0.0f;
        if (gr < cnt) v = S[(size_t)c_idx(ib[gr]) * 1024 + c0 + c];
        sm[r][c] = v;
    }
    __syncthreads();
    __half* Hb = H + (size_t)b * 2048 * 1024;
    __half* Lb = L + (size_t)b * 2048 * 1024;
#pragma unroll
    for (int k = 0; k < 4; k++) {
        int id = k * 1024 + t * 4;
        int r = id >> 6, c = id & 63;
        __half h[4], l[4];
#pragma unroll
        for (int q = 0; q < 4; q++) split2h(sm[r][c + q], h[q], l[q]);
        ushort4 Hp = { __half_as_ushort(h[0]), __half_as_ushort(h[1]),
                       __half_as_ushort(h[2]), __half_as_ushort(h[3]) };
        ushort4 Lp = { __half_as_ushort(l[0]), __half_as_ushort(l[1]),
                       __half_as_ushort(l[2]), __half_as_ushort(l[3]) };
        size_t o = (size_t)(r0 + r) * 1024 + c0 + c;
        *reinterpret_cast<ushort4*>(Hb + o) = Hp;
        *reinterpret_cast<ushort4*>(Lb + o) = Lp;
    }
    __half* HTb = HT + (size_t)b * 1024 * 2048;
#pragma unroll
    for (int k = 0; k < 4; k++) {
        int id = k * 1024 + t * 4;
        int c = id >> 6, r = id & 63;
        __half h[4];
#pragma unroll
        for (int q = 0; q < 4; q++) h[q] = __float2half_rn(sm[r + q][c]);
        ushort4 Hp = { __half_as_ushort(h[0]), __half_as_ushort(h[1]),
                       __half_as_ushort(h[2]), __half_as_ushort(h[3]) };
        size_t o = (size_t)(c0 + c) * 2048 + r0 + r;
        *reinterpret_cast<ushort4*>(HTb + o) = Hp;
    }
}

// ============================ fused row softmax (compact) =========================
__global__ void row_softmax_kernel() {
    const int b = blockIdx.y;
    const int row = blockIdx.x;
    if (row >= c_pad(g_cntXp[b])) return;
    const int nYp = c_pad(g_cntYp[b]);
    const float* sp = g_s + (size_t)b * 2048 * 2048 + (size_t)row * 2048;
    const int t = threadIdx.x;
    const bool act = (t * 8) < nYp;
    float v[8];
    if (act) {
        *reinterpret_cast<float4*>(&v[0]) = *reinterpret_cast<const float4*>(sp + t * 8);
        *reinterpret_cast<float4*>(&v[4]) = *reinterpret_cast<const float4*>(sp + t * 8 + 4);
    } else {
#pragma unroll
        for (int r = 0; r < 8; r++) v[r] = NEGV;
    }
    float m = v[0];
#pragma unroll
    for (int r = 1; r < 8; r++) m = fmaxf(m, v[r]);
    __shared__ float red[256];
    red[t] = m; __syncthreads();
    for (int s = 128; s > 0; s >>= 1) { if (t < s) red[t] = fmaxf(red[t], red[t + s]); __syncthreads(); }
    const float rm = red[0]; __syncthreads();
    float p[8], sum = 0.f;
#pragma unroll
    for (int r = 0; r < 8; r++) { p[r] = __expf(v[r] - rm); sum += p[r]; }
    red[t] = sum; __syncthreads();
    for (int s = 128; s > 0; s >>= 1) { if (t < s) red[t] += red[t + s]; __syncthreads(); }
    const float ri = (red[0] > 0.f) ? 1.0f / red[0] : 0.f;
    if (!act) return;
    size_t o = (size_t)b * 2048 * 2048 + (size_t)row * 2048 + t * 8;
#pragma unroll
    for (int g = 0; g < 2; g++) {
        __half h[4], l[4];
#pragma unroll
        for (int q = 0; q < 4; q++) split2h(p[g * 4 + q] * ri, h[q], l[q]);
        ushort4 Hp = { __half_as_ushort(h[0]), __half_as_ushort(h[1]),
                       __half_as_ushort(h[2]), __half_as_ushort(h[3]) };
        ushort4 Lp = { __half_as_ushort(l[0]), __half_as_ushort(l[1]),
                       __half_as_ushort(l[2]), __half_as_ushort(l[3]) };
        *reinterpret_cast<ushort4*>(g_Phi + o + g * 4) = Hp;
        *reinterpret_cast<ushort4*>(g_Plo + o + g * 4) = Lp;
    }
}

// ============================ col softmax stats (compact) =========================
__global__ void col_stats_kernel() {
    const int b = blockIdx.y;
    if (blockIdx.x * 32 >= c_pad(g_cntYp[b])) return;
    const int tx = threadIdx.x, ty = threadIdx.y;
    const int j = blockIdx.x * 32 + tx;
    const int nXp = c_pad(g_cntXp[b]);
    const float* sp = g_s + (size_t)b * 2048 * 2048 + j;
    float m = -3e38f;
    for (int i = ty; i < nXp; i += 8) m = fmaxf(m, sp[(size_t)i * 2048]);
    __shared__ float red[8][32];
    red[ty][tx] = m; __syncthreads();
    if (ty == 0) {
        float mm = red[0][tx];
#pragma unroll
        for (int r = 1; r < 8; r++) mm = fmaxf(mm, red[r][tx]);
        red[0][tx] = mm;
    }
    __syncthreads();
    const float cm = red[0][tx]; __syncthreads();
    float sum = 0.f;
    for (int i = ty; i < nXp; i += 8) sum += __expf(sp[(size_t)i * 2048] - cm);
    red[ty][tx] = sum; __syncthreads();
    if (ty == 0) {
        float ss = red[0][tx];
#pragma unroll
        for (int r = 1; r < 8; r++) ss += red[r][tx];
        g_cmax[b * 2048 + j] = cm;
        g_cinv[b * 2048 + j] = (ss > 0.f) ? 1.0f / ss : 0.f;
    }
}

__global__ void exp_colT_kernel() {
    const int b = blockIdx.z;
    const int i0 = blockIdx.x * 32, j0 = blockIdx.y * 32;
    if (i0 >= c_pad(g_cntXp[b]) || j0 >= c_pad(g_cntYp[b])) return;
    __shared__ float sm[32][33];
    const int tx = threadIdx.x, ty = threadIdx.y;
    const float* S = g_s + (size_t)b * 2048 * 2048;
    const int j = j0 + tx;
    const float cm = g_cmax[b * 2048 + j], ci = g_cinv[b * 2048 + j];
#pragma unroll
    for (int k = 0; k < 4; k++) {
        int i = ty * 4 + k;
        float v = S[(size_t)(i0 + i) * 2048 + j];
        sm[tx][i] = __expf(v - cm) * ci;
    }
    __syncthreads();
#pragma unroll
    for (int k = 0; k < 4; k++) {
        int jj = ty * 4 + k;
        float v = sm[jj][tx];
        __half h, l; split2h(v, h, l);
        size_t o = (size_t)b * 2048 * 2048 + (size_t)(j0 + jj) * 2048 + i0 + tx;
        g_Pchi[o] = h; g_Pclo[o] = l;
    }
}

// ============================ mean + fill kernels (merged) ========================
__global__ void mean_kernel(const float* __restrict__ x, const float* __restrict__ y) {
    const int zz = blockIdx.y;                // 0..31: <16 -> y->meanY, >=16 -> x->meanX
    const int b = zz & 15;
    const float* src = (zz < 16) ? y : x;
    float* dst = (zz < 16) ? g_meanY : g_meanX;
    const int d = blockIdx.x * 256 + threadIdx.x;
    const float* S = src + (size_t)b * 2048 * 1024 + d;
    float s0 = 0, s1 = 0, s2 = 0, s3 = 0;
    for (int i = 0; i < 2048; i += 4) {
        s0 += S[(size_t)i * 1024];
        s1 += S[(size_t)(i + 1) * 1024];
        s2 += S[(size_t)(i + 2) * 1024];
        s3 += S[(size_t)(i + 3) * 1024];
    }
    dst[b * 1024 + d] = (s0 + s1 + s2 + s3) * (1.0f / 2048.0f);
}

__global__ void mean_fill_kernel(const void* __restrict__ xm, const void* __restrict__ ym,
                                 float* __restrict__ out) {
    const int zz = blockIdx.y;                // <16: xm/meanY/out ; >=16: ym/meanX/out+33M
    const int b = zz & 15;
    const void* mask = (zz < 16) ? xm : ym;
    const float* mean = (zz < 16) ? g_meanY : g_meanX;
    float* dst = out + ((zz < 16) ? 0 : 33554432);
    const int i = blockIdx.x;
    if (!mask_at(mask, b * 2048 + i, g_mask_mode)) return;
    const int t = threadIdx.x;
    float4 v = *reinterpret_cast<const float4*>(mean + b * 1024 + t * 4);
    *reinterpret_cast<float4*>(dst + (size_t)b * 2048 * 1024 + (size_t)i * 1024 + t * 4) = v;
}

// ============ HMMA split GEMM: 3-stage pipeline, swizzled smem, occupancy 2 =======
// which: 0 = merged proj (3-term), 2 = score (3-term), 3 = merged attn (2-term)
__global__ __launch_bounds__(256, 2)
void gemm_hmma_kernel(int which, float* __restrict__ Cout)
{
    const int zz = blockIdx.z;
    const int sel = (which == 2) ? 0 : (zz >> 4);
    const int b = (which == 2) ? zz : (zz & 15);
    const int m0 = blockIdx.y * 128, n0 = blockIdx.x * 128;

    const __half *Ah, *Al, *Bh, *Bl;
    __half *Chi = nullptr, *Clo = nullptr;
    float* C = Cout;
    int lda, ldb, K, ldc, mode;
    int Mlim, Nlim = 1 << 30;
    int cRow = 0, cCol = 0;
    int nt3 = 1;
    const int* scat = nullptr;
    size_t sAb, sBb, cOff;

    if (which == 0) {
        if (sel == 0) { Ah = g_xhi; Al = g_xlo; Bh = g_wxhi; Bl = g_wxlo;
                        Mlim = c_pad(g_cntXp[b]); Chi = g_pxhi; Clo = g_pxlo; }
        else          { Ah = g_yhi; Al = g_ylo; Bh = g_wyhi; Bl = g_wylo;
                        Mlim = c_pad(g_cntYp[b]); Chi = g_pyhi; Clo = g_pylo; }
        lda = 1024; ldb = 1024; K = 1024; ldc = 1024; mode = 0;
        sAb = (size_t)2048 * 1024; sBb = 0; cOff = (size_t)b * 2048 * 1024;
    } else if (which == 2) {
        Ah = g_pxhi; Al = g_pxlo; Bh = g_pyhi; Bl = g_pylo;
        lda = 1024; ldb = 1024; K = 1024; ldc = 2048; mode = 1;
        Mlim = c_pad(g_cntXp[b]); Nlim = c_pad(g_cntYp[b]);
        cRow = c_cnt(g_cntX[b]); cCol = c_cnt(g_cntY[b]);
        C = g_s; sAb = (size_t)2048 * 1024; sBb = (size_t)2048 * 1024;
        cOff = (size_t)b * 2048 * 2048;
    } else {
        nt3 = 0;   // 2-term: (Phi + Plo) x y_hi
        if (sel == 0) {
            Ah = g_Phi; Al = g_Plo; Bh = g_yThi; Bl = g_yThi;
            Mlim = c_pad(g_cntXp[b]); K = c_pad(g_cntYp[b]);
            cRow = c_cnt(g_cntX[b]); scat = g_idxX + b * 2048;
            cOff = (size_t)b * 2048 * 1024;
        } else {
            Ah = g_Pchi; Al = g_Pclo; Bh = g_xThi; Bl = g_xThi;
            Mlim = c_pad(g_cntYp[b]); K = c_pad(g_cntXp[b]);
            cRow = c_cnt(g_cntY[b]); scat = g_idxY + b * 2048;
            cOff = (size_t)33554432 + (size_t)b * 2048 * 1024;
        }
        lda = 2048; ldb = 2048; ldc = 1024; mode = 2;
        sAb = (size_t)2048 * 2048; sBb = (size_t)1024 * 2048;
    }
    if (m0 >= Mlim || n0 >= Nlim) return;

    extern __shared__ __align__(16) char smem_raw[];
    const uint32_t sb = smem_u32(smem_raw);
    const int tid = threadIdx.x, wid = tid >> 5, lane = tid & 31;
    const int warp_m = wid & 3, warp_n = wid >> 2;

    const __half* tp[4] = {
        Ah + (size_t)b * sAb + (size_t)m0 * lda,
        Al + (size_t)b * sAb + (size_t)m0 * lda,
        Bh + (size_t)b * sBb + (size_t)n0 * ldb,
        Bl + (size_t)b * sBb + (size_t)n0 * ldb
    };

    float acc[2][8][4];
#pragma unroll
    for (int i = 0; i < 2; i++)
#pragma unroll
        for (int j = 0; j < 8; j++)
#pragma unroll
            for (int q = 0; q < 4; q++) acc[i][j][q] = 0.0f;

    const int rowA = warp_m * 32 + (lane & 7) + ((lane >> 3) & 1) * 8;
    const int cA = (rowA >> 1) & 3;
    const uint32_t aoff = (uint32_t)rowA * 64 + (uint32_t)((((lane >> 4) & 1) ^ (cA & 1)) * 16);
    const uint32_t sxA = (uint32_t)(cA >> 1);
    const int rowB = warp_n * 64 + (lane & 7) + ((lane >> 4) & 1) * 8;
    const int cB = (rowB >> 1) & 3;
    const uint32_t boff = (uint32_t)rowB * 64 + (uint32_t)((((lane >> 3) & 1) ^ (cB & 1)) * 16);
    const uint32_t sxB = (uint32_t)(cB >> 1);

    const int NC = K >> 5;    // clamped K -> NC in [4,64]
    const int nld = nt3 ? 8 : 6;

    auto load_chunk = [&](int ch, int buf) {
#pragma unroll
        for (int i = 0; i < 8; i++) {
            if (i >= nld) break;
            const int o = i >> 1;
            const int idx = ((i & 1) << 8) + tid;
            const int row = idx >> 2, gr = idx & 3;
            const __half* src = tp[o] + (size_t)row * (o < 2 ? lda : ldb) + ch * 32 + gr * 8;
            const uint32_t dst = sb + (uint32_t)buf * 32768 + (uint32_t)o * 8192
                               + (uint32_t)row * 64 + (uint32_t)((gr ^ ((row >> 1) & 3)) * 16);
            asm volatile("cp.async.cg.shared.global [%0], [%1], 16;" :: "r"(dst), "l"(src));
        }
        asm volatile("cp.async.commit_group;");
    };

    load_chunk(0, 0);
    load_chunk(1, 1);
    int cbuf = 0, pbuf = 2;
    for (int ch = 0; ch < NC; ch++) {
        __syncthreads();                         // pbuf free (consumed at ch-1)
        if (ch + 2 < NC) {
            load_chunk(ch + 2, pbuf);
            asm volatile("cp.async.wait_group 2;" ::: "memory");   // chunk ch landed
        } else if (ch + 1 < NC) {
            asm volatile("cp.async.wait_group 1;" ::: "memory");
        } else {
            asm volatile("cp.async.wait_group 0;" ::: "memory");
        }
        __syncthreads();                         // ch's data visible to all warps
        const uint32_t base = sb + (uint32_t)cbuf * 32768;
        if (++cbuf == 3) cbuf = 0;
        if (++pbuf == 3) pbuf = 0;
#pragma unroll
        for (int s = 0; s < 2; s++) {
            const uint32_t sA = ((uint32_t)s ^ sxA) << 5;
            const uint32_t sB = ((uint32_t)s ^ sxB) << 5;
            uint32_t a[2][2][4];
#pragma unroll
            for (int mf = 0; mf < 2; mf++) {
                LDSM4(a[mf][0], base + aoff + mf * 1024 + sA);
                LDSM4(a[mf][1], base + 8192 + aoff + mf * 1024 + sA);
            }
            uint32_t bh[2][4], bl[2][4];
            LDSM4(bh[0], base + 16384 + boff + sB);
            if (nt3) LDSM4(bl[0], base + 24576 + boff + sB);
#pragma unroll
            for (int np = 0; np < 4; np++) {
                const int cur = np & 1;
                if (np < 3) {
                    LDSM4(bh[cur ^ 1], base + 16384 + boff + (np + 1) * 1024 + sB);
                    if (nt3) LDSM4(bl[cur ^ 1], base + 24576 + boff + (np + 1) * 1024 + sB);
                }
#pragma unroll
                for (int mf = 0; mf < 2; mf++) {
#pragma unroll
                    for (int h = 0; h < 2; h++) {
                        const int nf = np * 2 + h;
                        MMA_F16(acc[mf][nf], a[mf][0], bh[cur][2 * h], bh[cur][2 * h + 1]);
                        if (nt3) MMA_F16(acc[mf][nf], a[mf][0], bl[cur][2 * h], bl[cur][2 * h + 1]);
                        MMA_F16(acc[mf][nf], a[mf][1], bh[cur][2 * h], bh[cur][2 * h + 1]);
                    }
                }
            }
        }
    }
    asm volatile("cp.async.wait_group 0;" ::: "memory");

    // ------------------------------ epilogue ------------------------------
    const int rg = m0 + warp_m * 32 + (lane >> 2);
    const int cg = n0 + warp_n * 64 + (lane & 3) * 2;

    if (mode == 0) {
        __half* CH = Chi + cOff;
        __half* CL = Clo + cOff;
#pragma unroll
        for (int mf = 0; mf < 2; mf++) {
#pragma unroll
            for (int nf = 0; nf < 8; nf++) {
                const int R = rg + mf * 16;
                const int C0 = cg + nf * 8;
                float r0 = fmaxf(acc[mf][nf][0], 0.f), r1 = fmaxf(acc[mf][nf][1], 0.f);
                float r2 = fmaxf(acc[mf][nf][2], 0.f), r3 = fmaxf(acc[mf][nf][3], 0.f);
                __half h0, l0, h1, l1, h2, l2, h3, l3;
                split2h(r0, h0, l0); split2h(r1, h1, l1);
                split2h(r2, h2, l2); split2h(r3, h3, l3);
                uint32_t hp0 = (uint32_t)__half_as_ushort(h0) | ((uint32_t)__half_as_ushort(h1) << 16);
                uint32_t lp0 = (uint32_t)__half_as_ushort(l0) | ((uint32_t)__half_as_ushort(l1) << 16);
                uint32_t hp1 = (uint32_t)__half_as_ushort(h2) | ((uint32_t)__half_as_ushort(h3) << 16);
                uint32_t lp1 = (uint32_t)__half_as_ushort(l2) | ((uint32_t)__half_as_ushort(l3) << 16);
                *reinterpret_cast<uint32_t*>(CH + (size_t)R * ldc + C0) = hp0;
                *reinterpret_cast<uint32_t*>(CL + (size_t)R * ldc + C0) = lp0;
                *reinterpret_cast<uint32_t*>(CH + (size_t)(R + 8) * ldc + C0) = hp1;
                *reinterpret_cast<uint32_t*>(CL + (size_t)(R + 8) * ldc + C0) = lp1;
            }
        }
    } else if (mode == 1) {
        float* Co = C + cOff;
#pragma unroll
        for (int mf = 0; mf < 2; mf++) {
#pragma unroll
            for (int nf = 0; nf < 8; nf++) {
                const int R0 = rg + mf * 16, R1 = R0 + 8;
                const int C0 = cg + nf * 8;
                const bool c0v = C0 < cCol, c1v = (C0 + 1) < cCol;
                const bool r0v = R0 < cRow, r1v = R1 < cRow;
                float2 w0 = { (r0v && c0v) ? acc[mf][nf][0] : NEGV,
                              (r0v && c1v) ? acc[mf][nf][1] : NEGV };
                float2 w1 = { (r1v && c0v) ? acc[mf][nf][2] : NEGV,
                              (r1v && c1v) ? acc[mf][nf][3] : NEGV };
                *reinterpret_cast<float2*>(Co + (size_t)R0 * ldc + C0) = w0;
                *reinterpret_cast<float2*>(Co + (size_t)R1 * ldc + C0) = w1;
            }
        }
    } else {
        float* Co = Cout + cOff;
        int gr[2][2];
#pragma unroll
        for (int mf = 0; mf < 2; mf++)
#pragma unroll
            for (int h = 0; h < 2; h++) {
                const int R = rg + mf * 16 + h * 8;
                gr[mf][h] = (R < cRow) ? c_idx(scat[R]) : -1;
            }
#pragma unroll
        for (int mf = 0; mf < 2; mf++) {
#pragma unroll
            for (int nf = 0; nf < 8; nf++) {
                const int C0 = cg + nf * 8;
                if (gr[mf][0] >= 0) {
                    float2 w = { acc[mf][nf][0], acc[mf][nf][1] };
                    *reinterpret_cast<float2*>(Co + (size_t)gr[mf][0] * 1024 + C0) = w;
                }
                if (gr[mf][1] >= 0) {
                    float2 w = { acc[mf][nf][2], acc[mf][nf][3] };
                    *reinterpret_cast<float2*>(Co + (size_t)gr[mf][1] * 1024 + C0) = w;
                }
            }
        }
    }
}

// =================================================================================
extern "C" void kernel_launch(void* const* d_in, const int* in_sizes, int n_in,
                              void* d_out, int out_size)
{
    (void)in_sizes; (void)n_in; (void)out_size;
    const float* x  = (const float*)d_in[0];
    const float* y  = (const float*)d_in[1];
    const void*  xm = d_in[2];
    const void*  ym = d_in[3];
    const float* Wx = (const float*)d_in[4];
    const float* Wy = (const float*)d_in[5];
    float* out = (float*)d_out;

    static const int SMEM_GEMM = 98304;   // 3 stages x 32768
    cudaFuncSetAttribute(gemm_hmma_kernel, cudaFuncAttributeMaxDynamicSharedMemorySize, SMEM_GEMM);

    // 0-2
    build_idx_kernel<<<32, 256>>>(xm, ym);
    gather_split_both_kernel<<<dim3(16, 32, 32), 256>>>(x, y);
    split_plain_kernel<<<2048, 256>>>(Wx, Wy);
    // 3: merged projection GEMM — ncu capture target
    gemm_hmma_kernel<<<dim3(8, 16, 32), 256, SMEM_GEMM>>>(0, nullptr);
    // score
    gemm_hmma_kernel<<<dim3(16, 16, 16), 256, SMEM_GEMM>>>(2, nullptr);
    // softmax passes
    row_softmax_kernel<<<dim3(2048, 16), 256>>>();
    col_stats_kernel<<<dim3(64, 16), dim3(32, 8)>>>();
    exp_colT_kernel<<<dim3(64, 64, 16), dim3(32, 8)>>>();
    // merged attention GEMMs (2-term, scatter epilogues)
    gemm_hmma_kernel<<<dim3(8, 16, 32), 256, SMEM_GEMM>>>(3, out);
    // masked rows: exact means
    mean_kernel<<<dim3(4, 32), 256>>>(x, y);
    mean_fill_kernel<<<dim3(2048, 32), 256>>>(xm, ym, out);
}